// round 5
// baseline (speedup 1.0000x reference)
#include <cuda_runtime.h>
#include <cuda_bf16.h>
#include <math.h>
#include <stdint.h>

#define BB  65536
#define DIN 128
#define HH  256
#define DE  64
#define KC  4096

// ---------------- scratch (static device globals; no allocation) ----------------
__device__ float g_h1[(size_t)BB * HH];
__device__ float g_h2[(size_t)BB * HH];
__device__ float g_z [(size_t)BB * DE];
__device__ float g_ps[512 * HH];
__device__ float g_pq[512 * HH];
__device__ float g_ps2[16 * HH];
__device__ float g_pq2[16 * HH];
__device__ float g_scale[HH];
__device__ float g_shift[HH];
__device__ float g_c2[KC];
__device__ int   g_idx[BB];
__device__ uint32_t g_cb32hi[32 * 8192];  // codebook tf32-hi fragments (k8), per chunk
__device__ uint32_t g_cb16hi[32 * 4096];  // codebook bf16(hi_t) fragments (k16)
__device__ uint32_t g_cb16lo[32 * 4096];  // codebook bf16(lo_t) fragments (k16)
__device__ int   g_nfb;                   // fallback row count
__device__ int   g_fbrows[BB];            // fallback row list

__device__ __forceinline__ uint32_t f2tf32(float v) {
    uint32_t r;
    asm("cvt.rna.tf32.f32 %0, %1;" : "=r"(r) : "f"(v));
    return r;
}
__device__ __forceinline__ uint32_t packbf16(float lo_even, float hi_odd) {
    __nv_bfloat162 t = __floats2bfloat162_rn(lo_even, hi_odd);  // x=low, y=high
    return *reinterpret_cast<uint32_t*>(&t);
}

// ================= double-buffered fp32 GEMM, 128x128 tile (R4, known-good) =====
template<int EPI, bool BNPRO, bool BNACC>
__global__ void __launch_bounds__(256, 2) sgemm128_kernel(
    const float* __restrict__ A, const float* __restrict__ Bm,
    const float* __restrict__ bias, float* __restrict__ C,
    float* __restrict__ ps, float* __restrict__ pq,
    int M, int N, int K)
{
    __shared__ float As[2][8][128];
    __shared__ float Bs[2][8][132];
    __shared__ float red[BNACC ? 2 * 16 * 128 : 1];
    __shared__ float ssc[BNPRO ? 256 : 1];
    __shared__ float ssh[BNPRO ? 256 : 1];

    const int tid = threadIdx.x;
    const int tx = tid & 15, ty = tid >> 4;
    const int m0 = blockIdx.y * 128, n0 = blockIdx.x * 128;
    const int ar = tid >> 1, ac = (tid & 1) * 4;
    const int br = tid >> 5, bc = (tid & 31) * 4;

    if (BNPRO) {
        ssc[tid] = g_scale[tid];
        ssh[tid] = g_shift[tid];
        __syncthreads();
    }

    {
        float4 av = *reinterpret_cast<const float4*>(A + (size_t)(m0 + ar) * K + ac);
        if (BNPRO) {
            av.x = fmaxf(fmaf(av.x, ssc[ac + 0], ssh[ac + 0]), 0.f);
            av.y = fmaxf(fmaf(av.y, ssc[ac + 1], ssh[ac + 1]), 0.f);
            av.z = fmaxf(fmaf(av.z, ssc[ac + 2], ssh[ac + 2]), 0.f);
            av.w = fmaxf(fmaf(av.w, ssc[ac + 3], ssh[ac + 3]), 0.f);
        }
        float4 bv = *reinterpret_cast<const float4*>(Bm + (size_t)br * N + n0 + bc);
        As[0][ac + 0][ar] = av.x;
        As[0][ac + 1][ar] = av.y;
        As[0][ac + 2][ar] = av.z;
        As[0][ac + 3][ar] = av.w;
        *reinterpret_cast<float4*>(&Bs[0][br][bc]) = bv;
    }
    __syncthreads();

    float acc[8][8] = {};
    int buf = 0;

    for (int k0 = 8; k0 <= K; k0 += 8) {
        const bool has = (k0 < K);
        float4 av_n, bv_n;
        if (has) {
            av_n = *reinterpret_cast<const float4*>(A + (size_t)(m0 + ar) * K + (k0 + ac));
            if (BNPRO) {
                av_n.x = fmaxf(fmaf(av_n.x, ssc[k0 + ac + 0], ssh[k0 + ac + 0]), 0.f);
                av_n.y = fmaxf(fmaf(av_n.y, ssc[k0 + ac + 1], ssh[k0 + ac + 1]), 0.f);
                av_n.z = fmaxf(fmaf(av_n.z, ssc[k0 + ac + 2], ssh[k0 + ac + 2]), 0.f);
                av_n.w = fmaxf(fmaf(av_n.w, ssc[k0 + ac + 3], ssh[k0 + ac + 3]), 0.f);
            }
            bv_n = *reinterpret_cast<const float4*>(Bm + (size_t)(k0 + br) * N + (n0 + bc));
        }
        #pragma unroll
        for (int kk = 0; kk < 8; kk++) {
            float a[8], b[8];
            *reinterpret_cast<float4*>(&a[0]) = *reinterpret_cast<const float4*>(&As[buf][kk][ty * 8 + 0]);
            *reinterpret_cast<float4*>(&a[4]) = *reinterpret_cast<const float4*>(&As[buf][kk][ty * 8 + 4]);
            *reinterpret_cast<float4*>(&b[0]) = *reinterpret_cast<const float4*>(&Bs[buf][kk][tx * 8 + 0]);
            *reinterpret_cast<float4*>(&b[4]) = *reinterpret_cast<const float4*>(&Bs[buf][kk][tx * 8 + 4]);
            #pragma unroll
            for (int i = 0; i < 8; i++)
                #pragma unroll
                for (int j = 0; j < 8; j++)
                    acc[i][j] = fmaf(a[i], b[j], acc[i][j]);
        }
        if (has) {
            As[buf ^ 1][ac + 0][ar] = av_n.x;
            As[buf ^ 1][ac + 1][ar] = av_n.y;
            As[buf ^ 1][ac + 2][ar] = av_n.z;
            As[buf ^ 1][ac + 3][ar] = av_n.w;
            *reinterpret_cast<float4*>(&Bs[buf ^ 1][br][bc]) = bv_n;
            __syncthreads();
            buf ^= 1;
        }
    }

    float cs[8], cq[8];
    #pragma unroll
    for (int j = 0; j < 8; j++) { cs[j] = 0.f; cq[j] = 0.f; }

    #pragma unroll
    for (int i = 0; i < 8; i++) {
        const int m = m0 + ty * 8 + i;
        #pragma unroll
        for (int j = 0; j < 8; j++) {
            const int n = n0 + tx * 8 + j;
            float v = acc[i][j] + bias[n];
            if (EPI == 1) v = fmaxf(v, 0.f);
            C[(size_t)m * N + n] = v;
            if (BNACC) { cs[j] += v; cq[j] = fmaf(v, v, cq[j]); }
        }
    }

    if (BNACC) {
        #pragma unroll
        for (int j = 0; j < 8; j++) {
            red[ty * 128 + tx * 8 + j]        = cs[j];
            red[2048 + ty * 128 + tx * 8 + j] = cq[j];
        }
        __syncthreads();
        if (tid < 128) {
            float s = 0.f, q = 0.f;
            #pragma unroll
            for (int t = 0; t < 16; t++) {
                s += red[t * 128 + tid];
                q += red[2048 + t * 128 + tid];
            }
            ps[(size_t)blockIdx.y * HH + n0 + tid] = s;
            pq[(size_t)blockIdx.y * HH + n0 + tid] = q;
        }
    }
}

// ================= GEMM3: 128x64 tile, tanh epilogue (R4, known-good) =========
__global__ void __launch_bounds__(256, 2) sgemm_z_kernel(
    const float* __restrict__ A, const float* __restrict__ Bm,
    const float* __restrict__ bias, float* __restrict__ C, int K)
{
    __shared__ float As[2][8][128];
    __shared__ float Bs[2][8][68];

    const int tid = threadIdx.x;
    const int tx = tid & 7, ty = tid >> 3;
    const int m0 = blockIdx.x * 128;
    const int ar = tid >> 1, ac = (tid & 1) * 4;
    const int br = tid >> 5, bc = (tid & 31) * 2;

    {
        float4 av = *reinterpret_cast<const float4*>(A + (size_t)(m0 + ar) * K + ac);
        float2 bv = *reinterpret_cast<const float2*>(Bm + (size_t)br * DE + bc);
        As[0][ac + 0][ar] = av.x;
        As[0][ac + 1][ar] = av.y;
        As[0][ac + 2][ar] = av.z;
        As[0][ac + 3][ar] = av.w;
        *reinterpret_cast<float2*>(&Bs[0][br][bc]) = bv;
    }
    __syncthreads();

    float acc[4][8] = {};
    int buf = 0;

    for (int k0 = 8; k0 <= K; k0 += 8) {
        const bool has = (k0 < K);
        float4 av_n;
        float2 bv_n;
        if (has) {
            av_n = *reinterpret_cast<const float4*>(A + (size_t)(m0 + ar) * K + (k0 + ac));
            bv_n = *reinterpret_cast<const float2*>(Bm + (size_t)(k0 + br) * DE + bc);
        }
        #pragma unroll
        for (int kk = 0; kk < 8; kk++) {
            float a[4], b[8];
            *reinterpret_cast<float4*>(&a[0]) = *reinterpret_cast<const float4*>(&As[buf][kk][ty * 4]);
            *reinterpret_cast<float4*>(&b[0]) = *reinterpret_cast<const float4*>(&Bs[buf][kk][tx * 8 + 0]);
            *reinterpret_cast<float4*>(&b[4]) = *reinterpret_cast<const float4*>(&Bs[buf][kk][tx * 8 + 4]);
            #pragma unroll
            for (int i = 0; i < 4; i++)
                #pragma unroll
                for (int j = 0; j < 8; j++)
                    acc[i][j] = fmaf(a[i], b[j], acc[i][j]);
        }
        if (has) {
            As[buf ^ 1][ac + 0][ar] = av_n.x;
            As[buf ^ 1][ac + 1][ar] = av_n.y;
            As[buf ^ 1][ac + 2][ar] = av_n.z;
            As[buf ^ 1][ac + 3][ar] = av_n.w;
            *reinterpret_cast<float2*>(&Bs[buf ^ 1][br][bc]) = bv_n;
            __syncthreads();
            buf ^= 1;
        }
    }

    #pragma unroll
    for (int i = 0; i < 4; i++) {
        const int m = m0 + ty * 4 + i;
        #pragma unroll
        for (int j = 0; j < 8; j++) {
            const int n = tx * 8 + j;
            C[(size_t)m * DE + n] = tanhf(acc[i][j] + bias[n]);
        }
    }
}

// ---------------- BN finalize: parallel two-stage -----------------
__global__ void bn_stage1_kernel()
{
    const int j = threadIdx.x;
    const int b0 = blockIdx.x * 32;
    float s = 0.f, q = 0.f;
    #pragma unroll 8
    for (int r = 0; r < 32; r++) {
        s += g_ps[(size_t)(b0 + r) * HH + j];
        q += g_pq[(size_t)(b0 + r) * HH + j];
    }
    g_ps2[blockIdx.x * HH + j] = s;
    g_pq2[blockIdx.x * HH + j] = q;
}

__global__ void bn_stage2_kernel(const float* __restrict__ gamma,
                                 const float* __restrict__ beta)
{
    const int j = threadIdx.x;
    float s = 0.f, q = 0.f;
    #pragma unroll
    for (int b = 0; b < 16; b++) { s += g_ps2[b * HH + j]; q += g_pq2[b * HH + j]; }
    const float mean = s * (1.f / (float)BB);
    const float var  = q * (1.f / (float)BB) - mean * mean;
    const float inv  = rsqrtf(var + 1e-5f);
    const float sc   = gamma[j] * inv;
    g_scale[j] = sc;
    g_shift[j] = beta[j] - mean * sc;
}

// ---------------- codebook squared norms + counter reset -----------------
__global__ void c2_kernel(const float* __restrict__ cb)
{
    if (blockIdx.x == 0 && threadIdx.x == 0) g_nfb = 0;
    const int k = blockIdx.x * 256 + threadIdx.x;
    if (k < KC) {
        float s = 0.f;
        #pragma unroll
        for (int j = 0; j < DE; j++) {
            float v = cb[(size_t)k * DE + j];
            s = fmaf(v, v, s);
        }
        g_c2[k] = s;
    }
}

// ---------------- codebook -> fragment-order tf32-hi + bf16 hi/lo ----------
__global__ void cvt_cb_kernel(const float* __restrict__ cb)
{
    const int ch = blockIdx.x;
    const int tid = threadIdx.x;
    const float* src = cb + (size_t)ch * 8192;

    // tf32-hi fragments (k8 layout)
    #pragma unroll
    for (int t = 0; t < 32; t++) {
        const int lin = t * 256 + tid;
        const int n = lin >> 6, k = lin & 63;
        const uint32_t hi = f2tf32(src[lin]);
        const int nt = n >> 3, nn = n & 7;
        const int ks = k >> 3, kk = k & 7;
        const int o = ((nt * 8 + ks) * 32 + nn * 4 + (kk & 3)) * 2 + (kk >> 2);
        g_cb32hi[ch * 8192 + o] = hi;
    }

    // bf16 hi/lo fragments (k16 layout, pairs)
    #pragma unroll
    for (int t = 0; t < 16; t++) {
        const int lin = t * 256 + tid;
        const int n = lin >> 5, k2 = lin & 31;
        const float2 v = *reinterpret_cast<const float2*>(src + n * 64 + k2 * 2);
        const float h0 = __uint_as_float(f2tf32(v.x));
        const float h1 = __uint_as_float(f2tf32(v.y));
        const float l0 = v.x - h0, l1 = v.y - h1;
        const int nt = n >> 3, nn = n & 7;
        const int ks = k2 >> 3, p = k2 & 7;
        const int o = ((nt * 4 + ks) * 32 + nn * 4 + (p & 3)) * 2 + (p >> 2);
        g_cb16hi[ch * 4096 + o] = packbf16(h0, h1);
        g_cb16lo[ch * 4096 + o] = packbf16(l0, l1);
    }
}

// ================= dist + argmin: tf32 main + bf16 corrections ================
__device__ __forceinline__ void mma_tf32(float c[4], uint32_t a0, uint32_t a1,
                                         uint32_t a2, uint32_t a3,
                                         uint32_t b0, uint32_t b1) {
    asm volatile(
        "mma.sync.aligned.m16n8k8.row.col.f32.tf32.tf32.f32 "
        "{%0,%1,%2,%3}, {%4,%5,%6,%7}, {%8,%9}, {%0,%1,%2,%3};"
        : "+f"(c[0]), "+f"(c[1]), "+f"(c[2]), "+f"(c[3])
        : "r"(a0), "r"(a1), "r"(a2), "r"(a3), "r"(b0), "r"(b1));
}
__device__ __forceinline__ void mma_bf16(float c[4], uint32_t a0, uint32_t a1,
                                         uint32_t a2, uint32_t a3,
                                         uint32_t b0, uint32_t b1) {
    asm volatile(
        "mma.sync.aligned.m16n8k16.row.col.f32.bf16.bf16.f32 "
        "{%0,%1,%2,%3}, {%4,%5,%6,%7}, {%8,%9}, {%0,%1,%2,%3};"
        : "+f"(c[0]), "+f"(c[1]), "+f"(c[2]), "+f"(c[3])
        : "r"(a0), "r"(a1), "r"(a2), "r"(a3), "r"(b0), "r"(b1));
}

#define TAU_MARGIN 1e-4f

// smem layout (bytes)
#define D_A32  0          // 8mt x 8ks x 32 x 4 = 32KB (tf32 hi)
#define D_A16H 32768      // 8mt x 4ks x 32 x 4 = 16KB
#define D_A16L 49152
#define D_B32  65536      // 16nt x 8ks x 32 x 2 = 32KB
#define D_B16H 98304      // 16nt x 4ks x 32 x 2 = 16KB
#define D_B16L 114688
#define D_C2   131072
#define D_REDF 131584
#define D_REDF2 139776
#define D_REDI 147968
#define D_SMEM 156160

__global__ void __launch_bounds__(256, 1) dist_argmin_mma(
    const float* __restrict__ z, int* __restrict__ idxo)
{
    extern __shared__ char smem[];
    uint32_t* sA32  = (uint32_t*)(smem + D_A32);
    uint32_t* sA16h = (uint32_t*)(smem + D_A16H);
    uint32_t* sA16l = (uint32_t*)(smem + D_A16L);
    uint32_t* sB32  = (uint32_t*)(smem + D_B32);
    uint32_t* sB16h = (uint32_t*)(smem + D_B16H);
    uint32_t* sB16l = (uint32_t*)(smem + D_B16L);
    float*    c2s   = (float*)(smem + D_C2);
    float*    redF  = (float*)(smem + D_REDF);
    float*    redF2 = (float*)(smem + D_REDF2);
    int*      redI  = (int*)(smem + D_REDI);

    const int tid  = threadIdx.x;
    const int lane = tid & 31;
    const int wid  = tid >> 5;
    const int wr   = wid >> 2;
    const int wc   = wid & 3;
    const int row0 = blockIdx.x * 128;

    // ---- stage Z tile [128 x 64]: tf32-hi (k8 frags) + bf16 hi/lo (k16 frags) ----
    #pragma unroll
    for (int t = 0; t < 16; t++) {
        const int lin = t * 256 + tid;
        const int r = lin >> 5, k2 = lin & 31;
        const float2 v = *reinterpret_cast<const float2*>(z + (size_t)(row0 + r) * DE + k2 * 2);
        const uint32_t hi0 = f2tf32(v.x), hi1 = f2tf32(v.y);
        const float h0f = __uint_as_float(hi0), h1f = __uint_as_float(hi1);
        const float l0 = v.x - h0f, l1 = v.y - h1f;

        const int mt = r >> 4, rr = r & 15;
        // tf32 element 0: k = 2*k2
        {
            const int k = 2 * k2;
            const int ks = k >> 3, kk = k & 7;
            const int fl = (rr & 7) * 4 + (kk & 3);
            const int rg = (rr >> 3) + 2 * (kk >> 2);
            sA32[((mt * 8 + ks) * 32 + fl) * 4 + rg] = hi0;
        }
        // tf32 element 1: k = 2*k2+1
        {
            const int k = 2 * k2 + 1;
            const int ks = k >> 3, kk = k & 7;
            const int fl = (rr & 7) * 4 + (kk & 3);
            const int rg = (rr >> 3) + 2 * (kk >> 2);
            sA32[((mt * 8 + ks) * 32 + fl) * 4 + rg] = hi1;
        }
        // bf16 pair
        {
            const int ks = k2 >> 3, p = k2 & 7;
            const int ln = (rr & 7) * 4 + (p & 3);
            const int rg = ((p >> 2) << 1) | (rr >> 3);
            const int o = ((mt * 4 + ks) * 32 + ln) * 4 + rg;
            sA16h[o] = packbf16(h0f, h1f);
            sA16l[o] = packbf16(l0, l1);
        }
    }

    float best[8], best2[8];
    int   bi[8];
    #pragma unroll
    for (int s = 0; s < 8; s++) { best[s] = 3.4e38f; best2[s] = 3.4e38f; bi[s] = 0; }

    for (int ch = 0; ch < 32; ch++) {
        __syncthreads();
        // ---- copy pre-converted CB chunk fragments ----
        {
            const uint4* g32 = (const uint4*)(g_cb32hi + ch * 8192);  // 2048 uint4
            const uint4* g16h = (const uint4*)(g_cb16hi + ch * 4096); // 1024 uint4
            const uint4* g16l = (const uint4*)(g_cb16lo + ch * 4096);
            uint4* s32 = (uint4*)sB32;
            uint4* s16h = (uint4*)sB16h;
            uint4* s16l = (uint4*)sB16l;
            #pragma unroll
            for (int t = 0; t < 8; t++) s32[t * 256 + tid] = g32[t * 256 + tid];
            #pragma unroll
            for (int t = 0; t < 4; t++) {
                s16h[t * 256 + tid] = g16h[t * 256 + tid];
                s16l[t * 256 + tid] = g16l[t * 256 + tid];
            }
        }
        if (tid < 128) c2s[tid] = g_c2[ch * 128 + tid];
        __syncthreads();

        float acc[4][4][4];
        #pragma unroll
        for (int mt = 0; mt < 4; mt++)
            #pragma unroll
            for (int nt = 0; nt < 4; nt++)
                #pragma unroll
                for (int j = 0; j < 4; j++) acc[mt][nt][j] = 0.f;

        // ---- phase 1: tf32 hi.hi, 8 k8-steps ----
        #pragma unroll
        for (int ks = 0; ks < 8; ks++) {
            uint4 a[4];
            uint2 b[4];
            #pragma unroll
            for (int mt = 0; mt < 4; mt++)
                a[mt] = *reinterpret_cast<const uint4*>(sA32 + (((wr * 4 + mt) * 8 + ks) * 32 + lane) * 4);
            #pragma unroll
            for (int nt = 0; nt < 4; nt++)
                b[nt] = *reinterpret_cast<const uint2*>(sB32 + (((wc * 4 + nt) * 8 + ks) * 32 + lane) * 2);
            #pragma unroll
            for (int mt = 0; mt < 4; mt++)
                #pragma unroll
                for (int nt = 0; nt < 4; nt++)
                    mma_tf32(acc[mt][nt], a[mt].x, a[mt].y, a[mt].z, a[mt].w, b[nt].x, b[nt].y);
        }

        // ---- phase 2: bf16 corrections (hi.lo + lo.hi), 4 k16-steps ----
        #pragma unroll
        for (int ks = 0; ks < 4; ks++) {
            uint4 ah[4], al[4];
            uint2 bh[4], bl[4];
            #pragma unroll
            for (int mt = 0; mt < 4; mt++) {
                const int o = (((wr * 4 + mt) * 4 + ks) * 32 + lane) * 4;
                ah[mt] = *reinterpret_cast<const uint4*>(sA16h + o);
                al[mt] = *reinterpret_cast<const uint4*>(sA16l + o);
            }
            #pragma unroll
            for (int nt = 0; nt < 4; nt++) {
                const int o = (((wc * 4 + nt) * 4 + ks) * 32 + lane) * 2;
                bh[nt] = *reinterpret_cast<const uint2*>(sB16h + o);
                bl[nt] = *reinterpret_cast<const uint2*>(sB16l + o);
            }
            #pragma unroll
            for (int mt = 0; mt < 4; mt++)
                #pragma unroll
                for (int nt = 0; nt < 4; nt++)
                    mma_bf16(acc[mt][nt], ah[mt].x, ah[mt].y, ah[mt].z, ah[mt].w, bl[nt].x, bl[nt].y);
            #pragma unroll
            for (int mt = 0; mt < 4; mt++)
                #pragma unroll
                for (int nt = 0; nt < 4; nt++)
                    mma_bf16(acc[mt][nt], al[mt].x, al[mt].y, al[mt].z, al[mt].w, bh[nt].x, bh[nt].y);
        }

        // ---- epilogue: dist = c2 - 2*dot, top-2 per slot (index increasing) ----
        #pragma unroll
        for (int nt = 0; nt < 4; nt++) {
            const int ncol = wc * 32 + nt * 8 + 2 * (lane & 3);
            const float cc0 = c2s[ncol];
            const float cc1 = c2s[ncol + 1];
            const int gi = ch * 128 + ncol;
            #pragma unroll
            for (int mt = 0; mt < 4; mt++) {
                const float d0 = fmaf(-2.f, acc[mt][nt][0], cc0);
                const float d1 = fmaf(-2.f, acc[mt][nt][1], cc1);
                const float d2 = fmaf(-2.f, acc[mt][nt][2], cc0);
                const float d3 = fmaf(-2.f, acc[mt][nt][3], cc1);
                const int s0 = mt * 2, s1 = mt * 2 + 1;
                if (d0 < best[s0]) { best2[s0] = best[s0]; best[s0] = d0; bi[s0] = gi; }
                else if (d0 < best2[s0]) best2[s0] = d0;
                if (d1 < best[s0]) { best2[s0] = best[s0]; best[s0] = d1; bi[s0] = gi + 1; }
                else if (d1 < best2[s0]) best2[s0] = d1;
                if (d2 < best[s1]) { best2[s1] = best[s1]; best[s1] = d2; bi[s1] = gi; }
                else if (d2 < best2[s1]) best2[s1] = d2;
                if (d3 < best[s1]) { best2[s1] = best[s1]; best[s1] = d3; bi[s1] = gi + 1; }
                else if (d3 < best2[s1]) best2[s1] = d3;
            }
        }
    }

    __syncthreads();
    #pragma unroll
    for (int s = 0; s < 8; s++) {
        const int mt = s >> 1, half = s & 1;
        const int row = wr * 64 + mt * 16 + half * 8 + (lane >> 2);
        const int e = wc * 4 + (lane & 3);
        redF[row * 16 + e]  = best[s];
        redF2[row * 16 + e] = best2[s];
        redI[row * 16 + e]  = bi[s];
    }
    __syncthreads();
    if (tid < 128) {
        float m1 = 3.4e38f, m2 = 3.4e38f;
        int   m1i = 0x7fffffff;
        #pragma unroll
        for (int e = 0; e < 16; e++) {
            const float v  = redF[tid * 16 + e];
            const float v2 = redF2[tid * 16 + e];
            const int   iv = redI[tid * 16 + e];
            if (v < m1 || (v == m1 && iv < m1i)) {
                m2 = fminf(m2, m1);
                m1 = v; m1i = iv;
            } else {
                m2 = fminf(m2, v);
            }
            m2 = fminf(m2, v2);
        }
        idxo[row0 + tid] = m1i;
        if (m2 - m1 < TAU_MARGIN) {
            const int pos = atomicAdd(&g_nfb, 1);
            g_fbrows[pos] = row0 + tid;
        }
    }
}

// ================= exact fp32 fallback for small-margin rows ================
__global__ void __launch_bounds__(256) fallback_kernel(
    const float* __restrict__ z, const float* __restrict__ cb, int* __restrict__ idxo)
{
    __shared__ float zs[8][64];
    __shared__ int   rows[8];
    __shared__ float rv[8 * 256];
    __shared__ int   ri[8 * 256];

    const int tid = threadIdx.x;
    const int nfb = g_nfb;

    for (int g = blockIdx.x; g * 8 < nfb; g += gridDim.x) {
        const int nr = min(8, nfb - g * 8);
        if (tid < 8) rows[tid] = (tid < nr) ? g_fbrows[g * 8 + tid] : 0;
        __syncthreads();
        for (int i = tid; i < nr * 64; i += 256)
            zs[i >> 6][i & 63] = z[(size_t)rows[i >> 6] * DE + (i & 63)];
        __syncthreads();

        float bv[8];
        int   bix[8];
        #pragma unroll
        for (int r = 0; r < 8; r++) { bv[r] = 3.4e38f; bix[r] = 0x7fffffff; }

        for (int c = 0; c < 16; c++) {
            const int code = c * 256 + tid;   // increasing per thread
            const float4* cp = (const float4*)(cb + (size_t)code * DE);
            float d[8] = {};
            #pragma unroll
            for (int q = 0; q < 16; q++) {
                const float4 ev = cp[q];
                #pragma unroll
                for (int r = 0; r < 8; r++) {
                    const float4 zv = *reinterpret_cast<const float4*>(&zs[r][q * 4]);
                    float t0 = zv.x - ev.x, t1 = zv.y - ev.y;
                    float t2 = zv.z - ev.z, t3 = zv.w - ev.w;
                    d[r] = fmaf(t0, t0, d[r]);
                    d[r] = fmaf(t1, t1, d[r]);
                    d[r] = fmaf(t2, t2, d[r]);
                    d[r] = fmaf(t3, t3, d[r]);
                }
            }
            #pragma unroll
            for (int r = 0; r < 8; r++)
                if (d[r] < bv[r]) { bv[r] = d[r]; bix[r] = code; }
        }

        #pragma unroll
        for (int r = 0; r < 8; r++) { rv[r * 256 + tid] = bv[r]; ri[r * 256 + tid] = bix[r]; }
        __syncthreads();

        const int wid = tid >> 5, lane = tid & 31;
        if (wid < nr) {
            float mv = 3.4e38f;
            int   mi = 0x7fffffff;
            for (int e = lane; e < 256; e += 32) {
                const float v = rv[wid * 256 + e];
                const int   i = ri[wid * 256 + e];
                if (v < mv || (v == mv && i < mi)) { mv = v; mi = i; }
            }
            #pragma unroll
            for (int off = 16; off > 0; off >>= 1) {
                const float ov = __shfl_down_sync(0xffffffff, mv, off);
                const int   oi = __shfl_down_sync(0xffffffff, mi, off);
                if (ov < mv || (ov == mv && oi < mi)) { mv = ov; mi = oi; }
            }
            if (lane == 0) idxo[rows[wid]] = mi;
        }
        __syncthreads();
    }
}

// ---------------- output writer ----------------
__global__ void writeout_kernel(const float* __restrict__ cb,
                                float* __restrict__ outf, int* __restrict__ outi,
                                int mode)
{
    const int gid = blockIdx.x * 256 + threadIdx.x;
    const int row = gid >> 6, j = gid & 63;
    const int id = g_idx[row];
    if (mode == 0) {
        if (j == 0) outf[row] = (float)id;
        outf[BB + gid] = cb[(size_t)id * DE + j];
    } else if (mode == 1) {
        outf[gid] = cb[(size_t)id * DE + j];
    } else {
        if (j == 0) outi[row] = id;
    }
}

// ---------------- launch -----------------------------------------------------------
extern "C" void kernel_launch(void* const* d_in, const int* in_sizes, int n_in,
                              void* d_out, int out_size)
{
    const float* x     = (const float*)d_in[0];
    const float* W1    = (const float*)d_in[1];
    const float* b1    = (const float*)d_in[2];
    const float* gamma = (const float*)d_in[3];
    const float* beta  = (const float*)d_in[4];
    const float* W2    = (const float*)d_in[5];
    const float* b2    = (const float*)d_in[6];
    const float* W3    = (const float*)d_in[7];
    const float* b3    = (const float*)d_in[8];
    const float* cb    = (const float*)d_in[9];

    float *h1p = nullptr, *h2p = nullptr, *zp = nullptr, *psp = nullptr, *pqp = nullptr;
    int *idxp = nullptr;
    cudaGetSymbolAddress((void**)&h1p, g_h1);
    cudaGetSymbolAddress((void**)&h2p, g_h2);
    cudaGetSymbolAddress((void**)&zp,  g_z);
    cudaGetSymbolAddress((void**)&psp, g_ps);
    cudaGetSymbolAddress((void**)&pqp, g_pq);
    cudaGetSymbolAddress((void**)&idxp, g_idx);

    cudaFuncSetAttribute(dist_argmin_mma, cudaFuncAttributeMaxDynamicSharedMemorySize, D_SMEM);

    dim3 blk(256);

    // codebook prep (also resets fallback counter)
    c2_kernel<<<KC / 256, 256>>>(cb);
    cvt_cb_kernel<<<32, 256>>>(cb);

    // h1 = x @ W1 + b1, fused BN partial sums
    sgemm128_kernel<0, false, true><<<dim3(HH / 128, BB / 128), blk>>>(
        x, W1, b1, h1p, psp, pqp, BB, HH, DIN);

    // BN finalize (parallel two-stage)
    bn_stage1_kernel<<<16, HH>>>();
    bn_stage2_kernel<<<1, HH>>>(gamma, beta);

    // h2 = relu( bnrelu(h1) @ W2 + b2 )
    sgemm128_kernel<1, true, false><<<dim3(HH / 128, BB / 128), blk>>>(
        h1p, W2, b2, h2p, nullptr, nullptr, BB, HH, HH);

    // z = tanh( h2 @ W3 + b3 )
    sgemm_z_kernel<<<BB / 128, blk>>>(h2p, W3, b3, zp, HH);

    // tensor-core dist/argmin + exact rescore of small-margin rows
    dist_argmin_mma<<<BB / 128, 256, D_SMEM>>>(zp, idxp);
    fallback_kernel<<<256, 256>>>(zp, cb, idxp);

    // outputs
    int mode;
    if      (out_size == BB * (DE + 1)) mode = 0;
    else if (out_size == BB * DE)       mode = 1;
    else                                mode = 2;
    writeout_kernel<<<(BB * DE) / 256, 256>>>(cb, (float*)d_out, (int*)d_out, mode);
}

// round 6
// speedup vs baseline: 1.4170x; 1.4170x over previous
#include <cuda_runtime.h>
#include <math.h>
#include <stdint.h>

#define BB  65536
#define DIN 128
#define HH  256
#define DE  64
#define KC  4096

// ---------------- scratch (static device globals; no allocation) ----------------
__device__ float g_h1[(size_t)BB * HH];
__device__ float g_h2[(size_t)BB * HH];
__device__ float g_z [(size_t)BB * DE];
__device__ float g_ps[512 * HH];
__device__ float g_pq[512 * HH];
__device__ float g_ps2[16 * HH];
__device__ float g_pq2[16 * HH];
__device__ float g_scale[HH];
__device__ float g_shift[HH];
__device__ float g_c2[KC];
__device__ int   g_idx[BB];
__device__ uint32_t g_cbhi[32 * 8192];   // codebook tf32-hi fragments (k8), per chunk
__device__ uint32_t g_cblo[32 * 8192];   // codebook tf32-lo fragments

__device__ __forceinline__ uint32_t f2tf32(float v) {
    uint32_t r;
    asm("cvt.rna.tf32.f32 %0, %1;" : "=r"(r) : "f"(v));
    return r;
}
__device__ __forceinline__ uint32_t smem_u32(const void* p) {
    uint32_t a;
    asm("{ .reg .u64 t; cvta.to.shared.u64 t, %1; cvt.u32.u64 %0, t; }" : "=r"(a) : "l"(p));
    return a;
}
__device__ __forceinline__ void cp16(uint32_t dst, const void* src) {
    asm volatile("cp.async.cg.shared.global [%0], [%1], 16;" :: "r"(dst), "l"(src));
}
#define CP_COMMIT() asm volatile("cp.async.commit_group;" ::: "memory")
#define CP_WAIT0()  asm volatile("cp.async.wait_group 0;" ::: "memory")

// ================= double-buffered fp32 GEMM, 128x128 tile (known-good) =====
template<int EPI, bool BNPRO, bool BNACC>
__global__ void __launch_bounds__(256, 2) sgemm128_kernel(
    const float* __restrict__ A, const float* __restrict__ Bm,
    const float* __restrict__ bias, float* __restrict__ C,
    float* __restrict__ ps, float* __restrict__ pq,
    int M, int N, int K)
{
    __shared__ float As[2][8][128];
    __shared__ float Bs[2][8][132];
    __shared__ float red[BNACC ? 2 * 16 * 128 : 1];
    __shared__ float ssc[BNPRO ? 256 : 1];
    __shared__ float ssh[BNPRO ? 256 : 1];

    const int tid = threadIdx.x;
    const int tx = tid & 15, ty = tid >> 4;
    const int m0 = blockIdx.y * 128, n0 = blockIdx.x * 128;
    const int ar = tid >> 1, ac = (tid & 1) * 4;
    const int br = tid >> 5, bc = (tid & 31) * 4;

    if (BNPRO) {
        ssc[tid] = g_scale[tid];
        ssh[tid] = g_shift[tid];
        __syncthreads();
    }

    {
        float4 av = *reinterpret_cast<const float4*>(A + (size_t)(m0 + ar) * K + ac);
        if (BNPRO) {
            av.x = fmaxf(fmaf(av.x, ssc[ac + 0], ssh[ac + 0]), 0.f);
            av.y = fmaxf(fmaf(av.y, ssc[ac + 1], ssh[ac + 1]), 0.f);
            av.z = fmaxf(fmaf(av.z, ssc[ac + 2], ssh[ac + 2]), 0.f);
            av.w = fmaxf(fmaf(av.w, ssc[ac + 3], ssh[ac + 3]), 0.f);
        }
        float4 bv = *reinterpret_cast<const float4*>(Bm + (size_t)br * N + n0 + bc);
        As[0][ac + 0][ar] = av.x;
        As[0][ac + 1][ar] = av.y;
        As[0][ac + 2][ar] = av.z;
        As[0][ac + 3][ar] = av.w;
        *reinterpret_cast<float4*>(&Bs[0][br][bc]) = bv;
    }
    __syncthreads();

    float acc[8][8] = {};
    int buf = 0;

    for (int k0 = 8; k0 <= K; k0 += 8) {
        const bool has = (k0 < K);
        float4 av_n, bv_n;
        if (has) {
            av_n = *reinterpret_cast<const float4*>(A + (size_t)(m0 + ar) * K + (k0 + ac));
            if (BNPRO) {
                av_n.x = fmaxf(fmaf(av_n.x, ssc[k0 + ac + 0], ssh[k0 + ac + 0]), 0.f);
                av_n.y = fmaxf(fmaf(av_n.y, ssc[k0 + ac + 1], ssh[k0 + ac + 1]), 0.f);
                av_n.z = fmaxf(fmaf(av_n.z, ssc[k0 + ac + 2], ssh[k0 + ac + 2]), 0.f);
                av_n.w = fmaxf(fmaf(av_n.w, ssc[k0 + ac + 3], ssh[k0 + ac + 3]), 0.f);
            }
            bv_n = *reinterpret_cast<const float4*>(Bm + (size_t)(k0 + br) * N + (n0 + bc));
        }
        #pragma unroll
        for (int kk = 0; kk < 8; kk++) {
            float a[8], b[8];
            *reinterpret_cast<float4*>(&a[0]) = *reinterpret_cast<const float4*>(&As[buf][kk][ty * 8 + 0]);
            *reinterpret_cast<float4*>(&a[4]) = *reinterpret_cast<const float4*>(&As[buf][kk][ty * 8 + 4]);
            *reinterpret_cast<float4*>(&b[0]) = *reinterpret_cast<const float4*>(&Bs[buf][kk][tx * 8 + 0]);
            *reinterpret_cast<float4*>(&b[4]) = *reinterpret_cast<const float4*>(&Bs[buf][kk][tx * 8 + 4]);
            #pragma unroll
            for (int i = 0; i < 8; i++)
                #pragma unroll
                for (int j = 0; j < 8; j++)
                    acc[i][j] = fmaf(a[i], b[j], acc[i][j]);
        }
        if (has) {
            As[buf ^ 1][ac + 0][ar] = av_n.x;
            As[buf ^ 1][ac + 1][ar] = av_n.y;
            As[buf ^ 1][ac + 2][ar] = av_n.z;
            As[buf ^ 1][ac + 3][ar] = av_n.w;
            *reinterpret_cast<float4*>(&Bs[buf ^ 1][br][bc]) = bv_n;
            __syncthreads();
            buf ^= 1;
        }
    }

    float cs[8], cq[8];
    #pragma unroll
    for (int j = 0; j < 8; j++) { cs[j] = 0.f; cq[j] = 0.f; }

    #pragma unroll
    for (int i = 0; i < 8; i++) {
        const int m = m0 + ty * 8 + i;
        #pragma unroll
        for (int j = 0; j < 8; j++) {
            const int n = n0 + tx * 8 + j;
            float v = acc[i][j] + bias[n];
            if (EPI == 1) v = fmaxf(v, 0.f);
            C[(size_t)m * N + n] = v;
            if (BNACC) { cs[j] += v; cq[j] = fmaf(v, v, cq[j]); }
        }
    }

    if (BNACC) {
        #pragma unroll
        for (int j = 0; j < 8; j++) {
            red[ty * 128 + tx * 8 + j]        = cs[j];
            red[2048 + ty * 128 + tx * 8 + j] = cq[j];
        }
        __syncthreads();
        if (tid < 128) {
            float s = 0.f, q = 0.f;
            #pragma unroll
            for (int t = 0; t < 16; t++) {
                s += red[t * 128 + tid];
                q += red[2048 + t * 128 + tid];
            }
            ps[(size_t)blockIdx.y * HH + n0 + tid] = s;
            pq[(size_t)blockIdx.y * HH + n0 + tid] = q;
        }
    }
}

// ================= GEMM3: 128x64 tile, tanh epilogue (known-good) =========
__global__ void __launch_bounds__(256, 2) sgemm_z_kernel(
    const float* __restrict__ A, const float* __restrict__ Bm,
    const float* __restrict__ bias, float* __restrict__ C, int K)
{
    __shared__ float As[2][8][128];
    __shared__ float Bs[2][8][68];

    const int tid = threadIdx.x;
    const int tx = tid & 7, ty = tid >> 3;
    const int m0 = blockIdx.x * 128;
    const int ar = tid >> 1, ac = (tid & 1) * 4;
    const int br = tid >> 5, bc = (tid & 31) * 2;

    {
        float4 av = *reinterpret_cast<const float4*>(A + (size_t)(m0 + ar) * K + ac);
        float2 bv = *reinterpret_cast<const float2*>(Bm + (size_t)br * DE + bc);
        As[0][ac + 0][ar] = av.x;
        As[0][ac + 1][ar] = av.y;
        As[0][ac + 2][ar] = av.z;
        As[0][ac + 3][ar] = av.w;
        *reinterpret_cast<float2*>(&Bs[0][br][bc]) = bv;
    }
    __syncthreads();

    float acc[4][8] = {};
    int buf = 0;

    for (int k0 = 8; k0 <= K; k0 += 8) {
        const bool has = (k0 < K);
        float4 av_n;
        float2 bv_n;
        if (has) {
            av_n = *reinterpret_cast<const float4*>(A + (size_t)(m0 + ar) * K + (k0 + ac));
            bv_n = *reinterpret_cast<const float2*>(Bm + (size_t)(k0 + br) * DE + bc);
        }
        #pragma unroll
        for (int kk = 0; kk < 8; kk++) {
            float a[4], b[8];
            *reinterpret_cast<float4*>(&a[0]) = *reinterpret_cast<const float4*>(&As[buf][kk][ty * 4]);
            *reinterpret_cast<float4*>(&b[0]) = *reinterpret_cast<const float4*>(&Bs[buf][kk][tx * 8 + 0]);
            *reinterpret_cast<float4*>(&b[4]) = *reinterpret_cast<const float4*>(&Bs[buf][kk][tx * 8 + 4]);
            #pragma unroll
            for (int i = 0; i < 4; i++)
                #pragma unroll
                for (int j = 0; j < 8; j++)
                    acc[i][j] = fmaf(a[i], b[j], acc[i][j]);
        }
        if (has) {
            As[buf ^ 1][ac + 0][ar] = av_n.x;
            As[buf ^ 1][ac + 1][ar] = av_n.y;
            As[buf ^ 1][ac + 2][ar] = av_n.z;
            As[buf ^ 1][ac + 3][ar] = av_n.w;
            *reinterpret_cast<float2*>(&Bs[buf ^ 1][br][bc]) = bv_n;
            __syncthreads();
            buf ^= 1;
        }
    }

    #pragma unroll
    for (int i = 0; i < 4; i++) {
        const int m = m0 + ty * 4 + i;
        #pragma unroll
        for (int j = 0; j < 8; j++) {
            const int n = tx * 8 + j;
            C[(size_t)m * DE + n] = tanhf(acc[i][j] + bias[n]);
        }
    }
}

// ---------------- BN finalize: parallel two-stage -----------------
__global__ void bn_stage1_kernel()
{
    const int j = threadIdx.x;
    const int b0 = blockIdx.x * 32;
    float s = 0.f, q = 0.f;
    #pragma unroll 8
    for (int r = 0; r < 32; r++) {
        s += g_ps[(size_t)(b0 + r) * HH + j];
        q += g_pq[(size_t)(b0 + r) * HH + j];
    }
    g_ps2[blockIdx.x * HH + j] = s;
    g_pq2[blockIdx.x * HH + j] = q;
}

__global__ void bn_stage2_kernel(const float* __restrict__ gamma,
                                 const float* __restrict__ beta)
{
    const int j = threadIdx.x;
    float s = 0.f, q = 0.f;
    #pragma unroll
    for (int b = 0; b < 16; b++) { s += g_ps2[b * HH + j]; q += g_pq2[b * HH + j]; }
    const float mean = s * (1.f / (float)BB);
    const float var  = q * (1.f / (float)BB) - mean * mean;
    const float inv  = rsqrtf(var + 1e-5f);
    const float sc   = gamma[j] * inv;
    g_scale[j] = sc;
    g_shift[j] = beta[j] - mean * sc;
}

// ---------------- codebook squared norms -----------------
__global__ void c2_kernel(const float* __restrict__ cb)
{
    const int k = blockIdx.x * 256 + threadIdx.x;
    if (k < KC) {
        float s = 0.f;
        #pragma unroll
        for (int j = 0; j < DE; j++) {
            float v = cb[(size_t)k * DE + j];
            s = fmaf(v, v, s);
        }
        g_c2[k] = s;
    }
}

// ---------------- codebook -> tf32 hi/lo fragments (fragment order per chunk) ----
__global__ void cvt_cb_kernel(const float* __restrict__ cb)
{
    const int ch = blockIdx.x;
    const int tid = threadIdx.x;
    const float* src = cb + (size_t)ch * 8192;
    #pragma unroll
    for (int t = 0; t < 32; t++) {
        const int lin = t * 256 + tid;
        const int n = lin >> 6, k = lin & 63;
        const float v = src[lin];
        const uint32_t hi = f2tf32(v);
        const uint32_t lo = f2tf32(v - __uint_as_float(hi));
        const int nt = n >> 3, nn = n & 7;
        const int ks = k >> 3, kk = k & 7;
        const int o = ((nt * 8 + ks) * 32 + nn * 4 + (kk & 3)) * 2 + (kk >> 2);
        g_cbhi[ch * 8192 + o] = hi;
        g_cblo[ch * 8192 + o] = lo;
    }
}

// ================= mma.sync tf32 3x-split dist + argmin (cp.async pipelined) ====
__device__ __forceinline__ void mma_tf32(float c[4], uint32_t a0, uint32_t a1,
                                         uint32_t a2, uint32_t a3,
                                         uint32_t b0, uint32_t b1) {
    asm volatile(
        "mma.sync.aligned.m16n8k8.row.col.f32.tf32.tf32.f32 "
        "{%0,%1,%2,%3}, {%4,%5,%6,%7}, {%8,%9}, {%0,%1,%2,%3};"
        : "+f"(c[0]), "+f"(c[1]), "+f"(c[2]), "+f"(c[3])
        : "r"(a0), "r"(a1), "r"(a2), "r"(a3), "r"(b0), "r"(b1));
}

// smem layout (bytes)
#define D_A_HI 0                         // 32KB (z tf32-hi frags)
#define D_A_LO 32768                     // 32KB
#define D_BHI(buf) (65536 + (buf) * 65536)
#define D_BLO(buf) (D_BHI(buf) + 32768)
#define D_C2   196608                    // 2 x 128 floats
#define D_REDF 197632                    // 8KB
#define D_REDI 205824                    // 8KB
#define D_SMEM 214016

__global__ void __launch_bounds__(256, 1) dist_argmin_mma(
    const float* __restrict__ z, int* __restrict__ idxo)
{
    extern __shared__ char smem[];
    const uint32_t sb = smem_u32(smem);
    uint32_t* sAhi = (uint32_t*)(smem + D_A_HI);
    uint32_t* sAlo = (uint32_t*)(smem + D_A_LO);
    float*    c2s  = (float*)(smem + D_C2);
    float*    redF = (float*)(smem + D_REDF);
    int*      redI = (int*)(smem + D_REDI);

    const int tid  = threadIdx.x;
    const int lane = tid & 31;
    const int wid  = tid >> 5;
    const int wr   = wid >> 2;
    const int wc   = wid & 3;
    const int row0 = blockIdx.x * 128;

    // ---- kick off async prefetch of chunk 0 before anything else ----
    {
        const uint4* gh = (const uint4*)(g_cbhi);
        const uint4* gl = (const uint4*)(g_cblo);
        const uint32_t bh = sb + D_BHI(0);
        const uint32_t bl = sb + D_BLO(0);
        #pragma unroll
        for (int t = 0; t < 8; t++) {
            cp16(bh + (t * 256 + tid) * 16, gh + t * 256 + tid);
            cp16(bl + (t * 256 + tid) * 16, gl + t * 256 + tid);
        }
        if (tid < 32) cp16(sb + D_C2 + tid * 16, (const uint4*)g_c2 + tid);
        CP_COMMIT();
    }

    // ---- stage Z tile [128 x 64] into fragment-order hi/lo ----
    #pragma unroll
    for (int t = 0; t < 32; t++) {
        const int lin = t * 256 + tid;
        const int r = lin >> 6, k = lin & 63;
        const float v = z[(size_t)(row0 + r) * DE + k];
        const uint32_t hi = f2tf32(v);
        const uint32_t lo = f2tf32(v - __uint_as_float(hi));
        const int mt = r >> 4, rr = r & 15;
        const int ks = k >> 3, kk = k & 7;
        const int fl = (rr & 7) * 4 + (kk & 3);
        const int rg = (rr >> 3) + 2 * (kk >> 2);
        const int o  = ((mt * 8 + ks) * 32 + fl) * 4 + rg;
        sAhi[o] = hi;
        sAlo[o] = lo;
    }

    float bestv[8];
    int   besti[8];
    #pragma unroll
    for (int s = 0; s < 8; s++) { bestv[s] = 3.4e38f; besti[s] = 0; }

    for (int ch = 0; ch < 32; ch++) {
        const int buf = ch & 1;
        CP_WAIT0();
        __syncthreads();   // chunk `ch` fragments + c2 visible to all; prev buf reads done

        // prefetch next chunk into the other buffer (overlaps with MMA below)
        if (ch + 1 < 32) {
            const uint4* gh = (const uint4*)(g_cbhi + (ch + 1) * 8192);
            const uint4* gl = (const uint4*)(g_cblo + (ch + 1) * 8192);
            const uint32_t bh = sb + D_BHI(buf ^ 1);
            const uint32_t bl = sb + D_BLO(buf ^ 1);
            #pragma unroll
            for (int t = 0; t < 8; t++) {
                cp16(bh + (t * 256 + tid) * 16, gh + t * 256 + tid);
                cp16(bl + (t * 256 + tid) * 16, gl + t * 256 + tid);
            }
            if (tid < 32)
                cp16(sb + D_C2 + (buf ^ 1) * 512 + tid * 16,
                     (const uint4*)(g_c2 + (ch + 1) * 128) + tid);
            CP_COMMIT();
        }

        const uint32_t* sBhi = (const uint32_t*)(smem + D_BHI(buf));
        const uint32_t* sBlo = (const uint32_t*)(smem + D_BLO(buf));

        // ---- mma mainloop: 3 tf32 products x 8 k8-steps ----
        float acc[4][4][4];
        #pragma unroll
        for (int mt = 0; mt < 4; mt++)
            #pragma unroll
            for (int nt = 0; nt < 4; nt++)
                #pragma unroll
                for (int j = 0; j < 4; j++) acc[mt][nt][j] = 0.f;

        #pragma unroll
        for (int ks = 0; ks < 8; ks++) {
            uint4 ahi[4], alo[4];
            uint2 bhi[4], blo[4];
            #pragma unroll
            for (int mt = 0; mt < 4; mt++) {
                const int o = (((wr * 4 + mt) * 8 + ks) * 32 + lane) * 4;
                ahi[mt] = *reinterpret_cast<const uint4*>(sAhi + o);
                alo[mt] = *reinterpret_cast<const uint4*>(sAlo + o);
            }
            #pragma unroll
            for (int nt = 0; nt < 4; nt++) {
                const int o = (((wc * 4 + nt) * 8 + ks) * 32 + lane) * 2;
                bhi[nt] = *reinterpret_cast<const uint2*>(sBhi + o);
                blo[nt] = *reinterpret_cast<const uint2*>(sBlo + o);
            }
            #pragma unroll
            for (int mt = 0; mt < 4; mt++)
                #pragma unroll
                for (int nt = 0; nt < 4; nt++)
                    mma_tf32(acc[mt][nt], ahi[mt].x, ahi[mt].y, ahi[mt].z, ahi[mt].w,
                             bhi[nt].x, bhi[nt].y);
            #pragma unroll
            for (int mt = 0; mt < 4; mt++)
                #pragma unroll
                for (int nt = 0; nt < 4; nt++)
                    mma_tf32(acc[mt][nt], ahi[mt].x, ahi[mt].y, ahi[mt].z, ahi[mt].w,
                             blo[nt].x, blo[nt].y);
            #pragma unroll
            for (int mt = 0; mt < 4; mt++)
                #pragma unroll
                for (int nt = 0; nt < 4; nt++)
                    mma_tf32(acc[mt][nt], alo[mt].x, alo[mt].y, alo[mt].z, alo[mt].w,
                             bhi[nt].x, bhi[nt].y);
        }

        // ---- epilogue: dist = c2 - 2*dot, per-slot argmin (index increasing) ----
        const float* c2p = c2s + buf * 128;
        #pragma unroll
        for (int nt = 0; nt < 4; nt++) {
            const int ncol = wc * 32 + nt * 8 + 2 * (lane & 3);
            const float cc0 = c2p[ncol];
            const float cc1 = c2p[ncol + 1];
            const int gi = ch * 128 + ncol;
            #pragma unroll
            for (int mt = 0; mt < 4; mt++) {
                const float d0 = fmaf(-2.f, acc[mt][nt][0], cc0);
                const float d1 = fmaf(-2.f, acc[mt][nt][1], cc1);
                const float d2 = fmaf(-2.f, acc[mt][nt][2], cc0);
                const float d3 = fmaf(-2.f, acc[mt][nt][3], cc1);
                const int s0 = mt * 2, s1 = mt * 2 + 1;
                if (d0 < bestv[s0]) { bestv[s0] = d0; besti[s0] = gi; }
                if (d1 < bestv[s0]) { bestv[s0] = d1; besti[s0] = gi + 1; }
                if (d2 < bestv[s1]) { bestv[s1] = d2; besti[s1] = gi; }
                if (d3 < bestv[s1]) { bestv[s1] = d3; besti[s1] = gi + 1; }
            }
        }
        __syncthreads();   // all reads of buf done before chunk ch+2 overwrites it
    }

    #pragma unroll
    for (int s = 0; s < 8; s++) {
        const int mt = s >> 1, half = s & 1;
        const int row = wr * 64 + mt * 16 + half * 8 + (lane >> 2);
        const int e = wc * 4 + (lane & 3);
        redF[row * 16 + e] = bestv[s];
        redI[row * 16 + e] = besti[s];
    }
    __syncthreads();
    if (tid < 128) {
        float bs = 3.4e38f;
        int   b  = 0x7fffffff;
        #pragma unroll
        for (int e = 0; e < 16; e++) {
            const float sv = redF[tid * 16 + e];
            const int   iv = redI[tid * 16 + e];
            if (sv < bs || (sv == bs && iv < b)) { bs = sv; b = iv; }
        }
        idxo[row0 + tid] = b;
    }
}

// ---------------- output writer ----------------
__global__ void writeout_kernel(const float* __restrict__ cb,
                                float* __restrict__ outf, int* __restrict__ outi,
                                int mode)
{
    const int gid = blockIdx.x * 256 + threadIdx.x;
    const int row = gid >> 6, j = gid & 63;
    const int id = g_idx[row];
    if (mode == 0) {
        if (j == 0) outf[row] = (float)id;
        outf[BB + gid] = cb[(size_t)id * DE + j];
    } else if (mode == 1) {
        outf[gid] = cb[(size_t)id * DE + j];
    } else {
        if (j == 0) outi[row] = id;
    }
}

// ---------------- launch -----------------------------------------------------------
extern "C" void kernel_launch(void* const* d_in, const int* in_sizes, int n_in,
                              void* d_out, int out_size)
{
    const float* x     = (const float*)d_in[0];
    const float* W1    = (const float*)d_in[1];
    const float* b1    = (const float*)d_in[2];
    const float* gamma = (const float*)d_in[3];
    const float* beta  = (const float*)d_in[4];
    const float* W2    = (const float*)d_in[5];
    const float* b2    = (const float*)d_in[6];
    const float* W3    = (const float*)d_in[7];
    const float* b3    = (const float*)d_in[8];
    const float* cb    = (const float*)d_in[9];

    float *h1p = nullptr, *h2p = nullptr, *zp = nullptr, *psp = nullptr, *pqp = nullptr;
    int *idxp = nullptr;
    cudaGetSymbolAddress((void**)&h1p, g_h1);
    cudaGetSymbolAddress((void**)&h2p, g_h2);
    cudaGetSymbolAddress((void**)&zp,  g_z);
    cudaGetSymbolAddress((void**)&psp, g_ps);
    cudaGetSymbolAddress((void**)&pqp, g_pq);
    cudaGetSymbolAddress((void**)&idxp, g_idx);

    cudaFuncSetAttribute(dist_argmin_mma, cudaFuncAttributeMaxDynamicSharedMemorySize, D_SMEM);

    dim3 blk(256);

    // h1 = x @ W1 + b1, fused BN partial sums        (launch 1)
    sgemm128_kernel<0, false, true><<<dim3(HH / 128, BB / 128), blk>>>(
        x, W1, b1, h1p, psp, pqp, BB, HH, DIN);

    // BN finalize (parallel two-stage)               (launches 2, 3)
    bn_stage1_kernel<<<16, HH>>>();
    bn_stage2_kernel<<<1, HH>>>(gamma, beta);

    // h2 = relu( bnrelu(h1) @ W2 + b2 )              (launch 4 — profiled slot)
    sgemm128_kernel<1, true, false><<<dim3(HH / 128, BB / 128), blk>>>(
        h1p, W2, b2, h2p, nullptr, nullptr, BB, HH, HH);

    // z = tanh( h2 @ W3 + b3 )                       (launch 5)
    sgemm_z_kernel<<<BB / 128, blk>>>(h2p, W3, b3, zp, HH);

    // codebook prep (needed only before dist)        (launches 6, 7)
    c2_kernel<<<KC / 256, 256>>>(cb);
    cvt_cb_kernel<<<32, 256>>>(cb);

    // tensor-core dist/argmin                        (launch 8)
    dist_argmin_mma<<<BB / 128, 256, D_SMEM>>>(zp, idxp);

    // outputs                                        (launch 9)
    int mode;
    if      (out_size == BB * (DE + 1)) mode = 0;
    else if (out_size == BB * DE)       mode = 1;
    else                                mode = 2;
    writeout_kernel<<<(BB * DE) / 256, 256>>>(cb, (float*)d_out, (int*)d_out, mode);
}

// round 7
// speedup vs baseline: 1.8210x; 1.2851x over previous
#include <cuda_runtime.h>
#include <cuda_fp16.h>
#include <math.h>
#include <stdint.h>

#define BB  65536
#define DIN 128
#define HH  256
#define DE  64
#define KC  4096

// ---------------- scratch (static device globals; no allocation) ----------------
__device__ float g_h1[(size_t)BB * HH];
__device__ float g_h2[(size_t)BB * HH];
__device__ float g_z [(size_t)BB * DE];
__device__ float g_ps[512 * HH];
__device__ float g_pq[512 * HH];
__device__ float g_ps2[16 * HH];
__device__ float g_pq2[16 * HH];
__device__ float g_scale[HH];
__device__ float g_shift[HH];
__device__ float g_c2[KC];
__device__ int   g_idx[BB];
__device__ uint32_t g_cb1[32 * 4096];   // codebook fp16-hi fragments (k16), per chunk
__device__ uint32_t g_cb2[32 * 4096];   // codebook fp16-lo fragments

__device__ __forceinline__ uint32_t smem_u32(const void* p) {
    uint32_t a;
    asm("{ .reg .u64 t; cvta.to.shared.u64 t, %1; cvt.u32.u64 %0, t; }" : "=r"(a) : "l"(p));
    return a;
}
__device__ __forceinline__ void cp16(uint32_t dst, const void* src) {
    asm volatile("cp.async.cg.shared.global [%0], [%1], 16;" :: "r"(dst), "l"(src));
}
#define CP_COMMIT() asm volatile("cp.async.commit_group;" ::: "memory")
#define CP_WAIT0()  asm volatile("cp.async.wait_group 0;" ::: "memory")

__device__ __forceinline__ uint32_t packh2(float a, float b) {
    __half2 t = __floats2half2_rn(a, b);   // x = a (low), y = b (high)
    return *reinterpret_cast<uint32_t*>(&t);
}

// ================= double-buffered fp32 GEMM, 128x128 tile (known-good) =====
template<int EPI, bool BNPRO, bool BNACC>
__global__ void __launch_bounds__(256, 2) sgemm128_kernel(
    const float* __restrict__ A, const float* __restrict__ Bm,
    const float* __restrict__ bias, float* __restrict__ C,
    float* __restrict__ ps, float* __restrict__ pq,
    int M, int N, int K)
{
    __shared__ float As[2][8][128];
    __shared__ float Bs[2][8][132];
    __shared__ float red[BNACC ? 2 * 16 * 128 : 1];
    __shared__ float ssc[BNPRO ? 256 : 1];
    __shared__ float ssh[BNPRO ? 256 : 1];

    const int tid = threadIdx.x;
    const int tx = tid & 15, ty = tid >> 4;
    const int m0 = blockIdx.y * 128, n0 = blockIdx.x * 128;
    const int ar = tid >> 1, ac = (tid & 1) * 4;
    const int br = tid >> 5, bc = (tid & 31) * 4;

    if (BNPRO) {
        ssc[tid] = g_scale[tid];
        ssh[tid] = g_shift[tid];
        __syncthreads();
    }

    {
        float4 av = *reinterpret_cast<const float4*>(A + (size_t)(m0 + ar) * K + ac);
        if (BNPRO) {
            av.x = fmaxf(fmaf(av.x, ssc[ac + 0], ssh[ac + 0]), 0.f);
            av.y = fmaxf(fmaf(av.y, ssc[ac + 1], ssh[ac + 1]), 0.f);
            av.z = fmaxf(fmaf(av.z, ssc[ac + 2], ssh[ac + 2]), 0.f);
            av.w = fmaxf(fmaf(av.w, ssc[ac + 3], ssh[ac + 3]), 0.f);
        }
        float4 bv = *reinterpret_cast<const float4*>(Bm + (size_t)br * N + n0 + bc);
        As[0][ac + 0][ar] = av.x;
        As[0][ac + 1][ar] = av.y;
        As[0][ac + 2][ar] = av.z;
        As[0][ac + 3][ar] = av.w;
        *reinterpret_cast<float4*>(&Bs[0][br][bc]) = bv;
    }
    __syncthreads();

    float acc[8][8] = {};
    int buf = 0;

    for (int k0 = 8; k0 <= K; k0 += 8) {
        const bool has = (k0 < K);
        float4 av_n, bv_n;
        if (has) {
            av_n = *reinterpret_cast<const float4*>(A + (size_t)(m0 + ar) * K + (k0 + ac));
            if (BNPRO) {
                av_n.x = fmaxf(fmaf(av_n.x, ssc[k0 + ac + 0], ssh[k0 + ac + 0]), 0.f);
                av_n.y = fmaxf(fmaf(av_n.y, ssc[k0 + ac + 1], ssh[k0 + ac + 1]), 0.f);
                av_n.z = fmaxf(fmaf(av_n.z, ssc[k0 + ac + 2], ssh[k0 + ac + 2]), 0.f);
                av_n.w = fmaxf(fmaf(av_n.w, ssc[k0 + ac + 3], ssh[k0 + ac + 3]), 0.f);
            }
            bv_n = *reinterpret_cast<const float4*>(Bm + (size_t)(k0 + br) * N + (n0 + bc));
        }
        #pragma unroll
        for (int kk = 0; kk < 8; kk++) {
            float a[8], b[8];
            *reinterpret_cast<float4*>(&a[0]) = *reinterpret_cast<const float4*>(&As[buf][kk][ty * 8 + 0]);
            *reinterpret_cast<float4*>(&a[4]) = *reinterpret_cast<const float4*>(&As[buf][kk][ty * 8 + 4]);
            *reinterpret_cast<float4*>(&b[0]) = *reinterpret_cast<const float4*>(&Bs[buf][kk][tx * 8 + 0]);
            *reinterpret_cast<float4*>(&b[4]) = *reinterpret_cast<const float4*>(&Bs[buf][kk][tx * 8 + 4]);
            #pragma unroll
            for (int i = 0; i < 8; i++)
                #pragma unroll
                for (int j = 0; j < 8; j++)
                    acc[i][j] = fmaf(a[i], b[j], acc[i][j]);
        }
        if (has) {
            As[buf ^ 1][ac + 0][ar] = av_n.x;
            As[buf ^ 1][ac + 1][ar] = av_n.y;
            As[buf ^ 1][ac + 2][ar] = av_n.z;
            As[buf ^ 1][ac + 3][ar] = av_n.w;
            *reinterpret_cast<float4*>(&Bs[buf ^ 1][br][bc]) = bv_n;
            __syncthreads();
            buf ^= 1;
        }
    }

    float cs[8], cq[8];
    #pragma unroll
    for (int j = 0; j < 8; j++) { cs[j] = 0.f; cq[j] = 0.f; }

    #pragma unroll
    for (int i = 0; i < 8; i++) {
        const int m = m0 + ty * 8 + i;
        #pragma unroll
        for (int j = 0; j < 8; j++) {
            const int n = n0 + tx * 8 + j;
            float v = acc[i][j] + bias[n];
            if (EPI == 1) v = fmaxf(v, 0.f);
            C[(size_t)m * N + n] = v;
            if (BNACC) { cs[j] += v; cq[j] = fmaf(v, v, cq[j]); }
        }
    }

    if (BNACC) {
        #pragma unroll
        for (int j = 0; j < 8; j++) {
            red[ty * 128 + tx * 8 + j]        = cs[j];
            red[2048 + ty * 128 + tx * 8 + j] = cq[j];
        }
        __syncthreads();
        if (tid < 128) {
            float s = 0.f, q = 0.f;
            #pragma unroll
            for (int t = 0; t < 16; t++) {
                s += red[t * 128 + tid];
                q += red[2048 + t * 128 + tid];
            }
            ps[(size_t)blockIdx.y * HH + n0 + tid] = s;
            pq[(size_t)blockIdx.y * HH + n0 + tid] = q;
        }
    }
}

// ================= GEMM3: 128x64 tile, tanh epilogue (known-good) =========
__global__ void __launch_bounds__(256, 2) sgemm_z_kernel(
    const float* __restrict__ A, const float* __restrict__ Bm,
    const float* __restrict__ bias, float* __restrict__ C, int K)
{
    __shared__ float As[2][8][128];
    __shared__ float Bs[2][8][68];

    const int tid = threadIdx.x;
    const int tx = tid & 7, ty = tid >> 3;
    const int m0 = blockIdx.x * 128;
    const int ar = tid >> 1, ac = (tid & 1) * 4;
    const int br = tid >> 5, bc = (tid & 31) * 2;

    {
        float4 av = *reinterpret_cast<const float4*>(A + (size_t)(m0 + ar) * K + ac);
        float2 bv = *reinterpret_cast<const float2*>(Bm + (size_t)br * DE + bc);
        As[0][ac + 0][ar] = av.x;
        As[0][ac + 1][ar] = av.y;
        As[0][ac + 2][ar] = av.z;
        As[0][ac + 3][ar] = av.w;
        *reinterpret_cast<float2*>(&Bs[0][br][bc]) = bv;
    }
    __syncthreads();

    float acc[4][8] = {};
    int buf = 0;

    for (int k0 = 8; k0 <= K; k0 += 8) {
        const bool has = (k0 < K);
        float4 av_n;
        float2 bv_n;
        if (has) {
            av_n = *reinterpret_cast<const float4*>(A + (size_t)(m0 + ar) * K + (k0 + ac));
            bv_n = *reinterpret_cast<const float2*>(Bm + (size_t)(k0 + br) * DE + bc);
        }
        #pragma unroll
        for (int kk = 0; kk < 8; kk++) {
            float a[4], b[8];
            *reinterpret_cast<float4*>(&a[0]) = *reinterpret_cast<const float4*>(&As[buf][kk][ty * 4]);
            *reinterpret_cast<float4*>(&b[0]) = *reinterpret_cast<const float4*>(&Bs[buf][kk][tx * 8 + 0]);
            *reinterpret_cast<float4*>(&b[4]) = *reinterpret_cast<const float4*>(&Bs[buf][kk][tx * 8 + 4]);
            #pragma unroll
            for (int i = 0; i < 4; i++)
                #pragma unroll
                for (int j = 0; j < 8; j++)
                    acc[i][j] = fmaf(a[i], b[j], acc[i][j]);
        }
        if (has) {
            As[buf ^ 1][ac + 0][ar] = av_n.x;
            As[buf ^ 1][ac + 1][ar] = av_n.y;
            As[buf ^ 1][ac + 2][ar] = av_n.z;
            As[buf ^ 1][ac + 3][ar] = av_n.w;
            *reinterpret_cast<float2*>(&Bs[buf ^ 1][br][bc]) = bv_n;
            __syncthreads();
            buf ^= 1;
        }
    }

    #pragma unroll
    for (int i = 0; i < 4; i++) {
        const int m = m0 + ty * 4 + i;
        #pragma unroll
        for (int j = 0; j < 8; j++) {
            const int n = tx * 8 + j;
            C[(size_t)m * DE + n] = tanhf(acc[i][j] + bias[n]);
        }
    }
}

// ---------------- BN finalize: parallel two-stage -----------------
__global__ void bn_stage1_kernel()
{
    const int j = threadIdx.x;
    const int b0 = blockIdx.x * 32;
    float s = 0.f, q = 0.f;
    #pragma unroll 8
    for (int r = 0; r < 32; r++) {
        s += g_ps[(size_t)(b0 + r) * HH + j];
        q += g_pq[(size_t)(b0 + r) * HH + j];
    }
    g_ps2[blockIdx.x * HH + j] = s;
    g_pq2[blockIdx.x * HH + j] = q;
}

__global__ void bn_stage2_kernel(const float* __restrict__ gamma,
                                 const float* __restrict__ beta)
{
    const int j = threadIdx.x;
    float s = 0.f, q = 0.f;
    #pragma unroll
    for (int b = 0; b < 16; b++) { s += g_ps2[b * HH + j]; q += g_pq2[b * HH + j]; }
    const float mean = s * (1.f / (float)BB);
    const float var  = q * (1.f / (float)BB) - mean * mean;
    const float inv  = rsqrtf(var + 1e-5f);
    const float sc   = gamma[j] * inv;
    g_scale[j] = sc;
    g_shift[j] = beta[j] - mean * sc;
}

// ---------------- codebook squared norms -----------------
__global__ void c2_kernel(const float* __restrict__ cb)
{
    const int k = blockIdx.x * 256 + threadIdx.x;
    if (k < KC) {
        float s = 0.f;
        #pragma unroll
        for (int j = 0; j < DE; j++) {
            float v = cb[(size_t)k * DE + j];
            s = fmaf(v, v, s);
        }
        g_c2[k] = s;
    }
}

// ---------------- codebook -> fp16 hi/lo fragments (m16n8k16 B layout) ----------
// B frag (k16 x n8, col): lane l -> n = l>>2, k-pair i = l&3;
// b0 = {B[2i][n], B[2i+1][n]} (= cb[n][2i], cb[n][2i+1]); b1 = k+8.
__global__ void cvt_cb_kernel(const float* __restrict__ cb)
{
    const int ch = blockIdx.x;
    const int tid = threadIdx.x;
    const float* src = cb + (size_t)ch * 8192;
    #pragma unroll
    for (int t = 0; t < 16; t++) {
        const int lin = t * 256 + tid;
        const int n = lin >> 5, k2 = lin & 31;           // k2 = k/2
        const float2 v = *reinterpret_cast<const float2*>(src + n * 64 + 2 * k2);
        const uint32_t h = packh2(v.x, v.y);
        const float r0 = v.x - __half2float(__float2half_rn(v.x));
        const float r1 = v.y - __half2float(__float2half_rn(v.y));
        const uint32_t l = packh2(r0, r1);
        const int nt = n >> 3, nn = n & 7;
        const int ks = k2 >> 3, kk2 = k2 & 7;            // 16 k (8 pairs) per kstep
        const int o = ((nt * 4 + ks) * 32 + nn * 4 + (kk2 & 3)) * 2 + (kk2 >> 2);
        g_cb1[ch * 4096 + o] = h;
        g_cb2[ch * 4096 + o] = l;
    }
}

// ================= mma.sync fp16 3-term split dist + argmin =================
__device__ __forceinline__ void mma_f16(float c[4], uint32_t a0, uint32_t a1,
                                        uint32_t a2, uint32_t a3,
                                        uint32_t b0, uint32_t b1) {
    asm volatile(
        "mma.sync.aligned.m16n8k16.row.col.f32.f16.f16.f32 "
        "{%0,%1,%2,%3}, {%4,%5,%6,%7}, {%8,%9}, {%0,%1,%2,%3};"
        : "+f"(c[0]), "+f"(c[1]), "+f"(c[2]), "+f"(c[3])
        : "r"(a0), "r"(a1), "r"(a2), "r"(a3), "r"(b0), "r"(b1));
}

// smem layout (bytes)
#define D_A1   0                        // 16KB: 8mt x 4ks x 32 lanes x 4 u32
#define D_A2   16384                    // 16KB
#define D_B1(buf) (32768 + (buf) * 32768)
#define D_B2(buf) (D_B1(buf) + 16384)
#define D_C2   98304                    // 2 x 128 floats
#define D_REDF 99328                    // 128 x 16 floats = 8KB
#define D_REDI 107520                   // 8KB
#define D_SMEM 115712

__global__ void __launch_bounds__(256, 1) dist_argmin_mma(
    const float* __restrict__ z, int* __restrict__ idxo)
{
    extern __shared__ char smem[];
    const uint32_t sb = smem_u32(smem);
    uint32_t* sA1 = (uint32_t*)(smem + D_A1);
    uint32_t* sA2 = (uint32_t*)(smem + D_A2);
    float*    c2s = (float*)(smem + D_C2);
    float*    redF = (float*)(smem + D_REDF);
    int*      redI = (int*)(smem + D_REDI);

    const int tid  = threadIdx.x;
    const int lane = tid & 31;
    const int wid  = tid >> 5;
    const int wr   = wid >> 2;
    const int wc   = wid & 3;
    const int row0 = blockIdx.x * 128;

    // ---- async prefetch of chunk 0 ----
    {
        const uint4* g1 = (const uint4*)(g_cb1);   // 1024 uint4
        const uint4* g2 = (const uint4*)(g_cb2);
        const uint32_t b1 = sb + D_B1(0);
        const uint32_t b2 = sb + D_B2(0);
        #pragma unroll
        for (int t = 0; t < 4; t++) {
            cp16(b1 + (t * 256 + tid) * 16, g1 + t * 256 + tid);
            cp16(b2 + (t * 256 + tid) * 16, g2 + t * 256 + tid);
        }
        if (tid < 32) cp16(sb + D_C2 + tid * 16, (const uint4*)g_c2 + tid);
        CP_COMMIT();
    }

    // ---- stage Z tile [128 x 64] into fp16 A fragments (hi + lo) ----
    // A frag (m16 x k16 row): lane l -> row g = l>>2, pair i = l&3;
    // a0={A[g][2i],A[g][2i+1]}, a1=row+8, a2=k+8, a3=row+8,k+8.
    #pragma unroll
    for (int t = 0; t < 16; t++) {
        const int lin = t * 256 + tid;
        const int r = lin >> 5, k2 = lin & 31;
        const float2 v = *reinterpret_cast<const float2*>(z + (size_t)(row0 + r) * DE + 2 * k2);
        const uint32_t h = packh2(v.x, v.y);
        const float r0 = v.x - __half2float(__float2half_rn(v.x));
        const float r1 = v.y - __half2float(__float2half_rn(v.y));
        const uint32_t l = packh2(r0, r1);
        const int mt = r >> 4, rr = r & 15;
        const int ks = k2 >> 3, kk2 = k2 & 7;
        const int ln = (rr & 7) * 4 + (kk2 & 3);
        const int rg = (rr >> 3) + 2 * (kk2 >> 2);
        const int o = ((mt * 4 + ks) * 32 + ln) * 4 + rg;
        sA1[o] = h;
        sA2[o] = l;
    }

    float bestv[8];
    int   besti[8];
    #pragma unroll
    for (int s = 0; s < 8; s++) { bestv[s] = 3.4e38f; besti[s] = 0; }

    for (int ch = 0; ch < 32; ch++) {
        const int buf = ch & 1;
        CP_WAIT0();
        __syncthreads();

        // prefetch next chunk (overlaps with MMA below)
        if (ch + 1 < 32) {
            const uint4* g1 = (const uint4*)(g_cb1 + (ch + 1) * 4096);
            const uint4* g2 = (const uint4*)(g_cb2 + (ch + 1) * 4096);
            const uint32_t b1 = sb + D_B1(buf ^ 1);
            const uint32_t b2 = sb + D_B2(buf ^ 1);
            #pragma unroll
            for (int t = 0; t < 4; t++) {
                cp16(b1 + (t * 256 + tid) * 16, g1 + t * 256 + tid);
                cp16(b2 + (t * 256 + tid) * 16, g2 + t * 256 + tid);
            }
            if (tid < 32)
                cp16(sb + D_C2 + (buf ^ 1) * 512 + tid * 16,
                     (const uint4*)(g_c2 + (ch + 1) * 128) + tid);
            CP_COMMIT();
        }

        const uint32_t* sB1 = (const uint32_t*)(smem + D_B1(buf));
        const uint32_t* sB2 = (const uint32_t*)(smem + D_B2(buf));

        // ---- mma mainloop: 3 fp16 products x 4 k16-steps ----
        float acc[4][4][4];
        #pragma unroll
        for (int mt = 0; mt < 4; mt++)
            #pragma unroll
            for (int nt = 0; nt < 4; nt++)
                #pragma unroll
                for (int j = 0; j < 4; j++) acc[mt][nt][j] = 0.f;

        #pragma unroll
        for (int ks = 0; ks < 4; ks++) {
            uint4 a1[4], a2[4];
            uint2 b1[4], b2[4];
            #pragma unroll
            for (int mt = 0; mt < 4; mt++) {
                const int o = (((wr * 4 + mt) * 4 + ks) * 32 + lane) * 4;
                a1[mt] = *reinterpret_cast<const uint4*>(sA1 + o);
                a2[mt] = *reinterpret_cast<const uint4*>(sA2 + o);
            }
            #pragma unroll
            for (int nt = 0; nt < 4; nt++) {
                const int o = (((wc * 4 + nt) * 4 + ks) * 32 + lane) * 2;
                b1[nt] = *reinterpret_cast<const uint2*>(sB1 + o);
                b2[nt] = *reinterpret_cast<const uint2*>(sB2 + o);
            }
            #pragma unroll
            for (int mt = 0; mt < 4; mt++)
                #pragma unroll
                for (int nt = 0; nt < 4; nt++)
                    mma_f16(acc[mt][nt], a1[mt].x, a1[mt].y, a1[mt].z, a1[mt].w,
                            b1[nt].x, b1[nt].y);
            #pragma unroll
            for (int mt = 0; mt < 4; mt++)
                #pragma unroll
                for (int nt = 0; nt < 4; nt++)
                    mma_f16(acc[mt][nt], a1[mt].x, a1[mt].y, a1[mt].z, a1[mt].w,
                            b2[nt].x, b2[nt].y);
            #pragma unroll
            for (int mt = 0; mt < 4; mt++)
                #pragma unroll
                for (int nt = 0; nt < 4; nt++)
                    mma_f16(acc[mt][nt], a2[mt].x, a2[mt].y, a2[mt].z, a2[mt].w,
                            b1[nt].x, b1[nt].y);
        }

        // ---- epilogue: dist = c2 - 2*dot, per-slot argmin (index increasing) ----
        const float* c2p = c2s + buf * 128;
        #pragma unroll
        for (int nt = 0; nt < 4; nt++) {
            const int ncol = wc * 32 + nt * 8 + 2 * (lane & 3);
            const float cc0 = c2p[ncol];
            const float cc1 = c2p[ncol + 1];
            const int gi = ch * 128 + ncol;
            #pragma unroll
            for (int mt = 0; mt < 4; mt++) {
                const float d0 = fmaf(-2.f, acc[mt][nt][0], cc0);
                const float d1 = fmaf(-2.f, acc[mt][nt][1], cc1);
                const float d2 = fmaf(-2.f, acc[mt][nt][2], cc0);
                const float d3 = fmaf(-2.f, acc[mt][nt][3], cc1);
                const int s0 = mt * 2, s1 = mt * 2 + 1;
                if (d0 < bestv[s0]) { bestv[s0] = d0; besti[s0] = gi; }
                if (d1 < bestv[s0]) { bestv[s0] = d1; besti[s0] = gi + 1; }
                if (d2 < bestv[s1]) { bestv[s1] = d2; besti[s1] = gi; }
                if (d3 < bestv[s1]) { bestv[s1] = d3; besti[s1] = gi + 1; }
            }
        }
        __syncthreads();
    }

    #pragma unroll
    for (int s = 0; s < 8; s++) {
        const int mt = s >> 1, half = s & 1;
        const int row = wr * 64 + mt * 16 + half * 8 + (lane >> 2);
        const int e = wc * 4 + (lane & 3);
        redF[row * 16 + e] = bestv[s];
        redI[row * 16 + e] = besti[s];
    }
    __syncthreads();
    if (tid < 128) {
        float bs = 3.4e38f;
        int   b  = 0x7fffffff;
        #pragma unroll
        for (int e = 0; e < 16; e++) {
            const float sv = redF[tid * 16 + e];
            const int   iv = redI[tid * 16 + e];
            if (sv < bs || (sv == bs && iv < b)) { bs = sv; b = iv; }
        }
        idxo[row0 + tid] = b;
    }
}

// ---------------- output writer ----------------
__global__ void writeout_kernel(const float* __restrict__ cb,
                                float* __restrict__ outf, int* __restrict__ outi,
                                int mode)
{
    const int gid = blockIdx.x * 256 + threadIdx.x;
    const int row = gid >> 6, j = gid & 63;
    const int id = g_idx[row];
    if (mode == 0) {
        if (j == 0) outf[row] = (float)id;
        outf[BB + gid] = cb[(size_t)id * DE + j];
    } else if (mode == 1) {
        outf[gid] = cb[(size_t)id * DE + j];
    } else {
        if (j == 0) outi[row] = id;
    }
}

// ---------------- launch -----------------------------------------------------------
extern "C" void kernel_launch(void* const* d_in, const int* in_sizes, int n_in,
                              void* d_out, int out_size)
{
    const float* x     = (const float*)d_in[0];
    const float* W1    = (const float*)d_in[1];
    const float* b1    = (const float*)d_in[2];
    const float* gamma = (const float*)d_in[3];
    const float* beta  = (const float*)d_in[4];
    const float* W2    = (const float*)d_in[5];
    const float* b2    = (const float*)d_in[6];
    const float* W3    = (const float*)d_in[7];
    const float* b3    = (const float*)d_in[8];
    const float* cb    = (const float*)d_in[9];

    float *h1p = nullptr, *h2p = nullptr, *zp = nullptr, *psp = nullptr, *pqp = nullptr;
    int *idxp = nullptr;
    cudaGetSymbolAddress((void**)&h1p, g_h1);
    cudaGetSymbolAddress((void**)&h2p, g_h2);
    cudaGetSymbolAddress((void**)&zp,  g_z);
    cudaGetSymbolAddress((void**)&psp, g_ps);
    cudaGetSymbolAddress((void**)&pqp, g_pq);
    cudaGetSymbolAddress((void**)&idxp, g_idx);

    cudaFuncSetAttribute(dist_argmin_mma, cudaFuncAttributeMaxDynamicSharedMemorySize, D_SMEM);

    dim3 blk(256);

    // h1 = x @ W1 + b1, fused BN partial sums
    sgemm128_kernel<0, false, true><<<dim3(HH / 128, BB / 128), blk>>>(
        x, W1, b1, h1p, psp, pqp, BB, HH, DIN);

    // BN finalize (parallel two-stage)
    bn_stage1_kernel<<<16, HH>>>();
    bn_stage2_kernel<<<1, HH>>>(gamma, beta);

    // h2 = relu( bnrelu(h1) @ W2 + b2 )
    sgemm128_kernel<1, true, false><<<dim3(HH / 128, BB / 128), blk>>>(
        h1p, W2, b2, h2p, nullptr, nullptr, BB, HH, HH);

    // z = tanh( h2 @ W3 + b3 )
    sgemm_z_kernel<<<BB / 128, blk>>>(h2p, W3, b3, zp, HH);

    // codebook prep
    c2_kernel<<<KC / 256, 256>>>(cb);
    cvt_cb_kernel<<<32, 256>>>(cb);

    // tensor-core dist/argmin (fp16 3-term split)
    dist_argmin_mma<<<BB / 128, 256, D_SMEM>>>(zp, idxp);

    // outputs
    int mode;
    if      (out_size == BB * (DE + 1)) mode = 0;
    else if (out_size == BB * DE)       mode = 1;
    else                                mode = 2;
    writeout_kernel<<<(BB * DE) / 256, 256>>>(cb, (float*)d_out, (int*)d_out, mode);
}

// round 8
// speedup vs baseline: 2.4498x; 1.3453x over previous
#include <cuda_runtime.h>
#include <cuda_fp16.h>
#include <math.h>
#include <stdint.h>

#define BB  65536
#define DIN 128
#define HH  256
#define DE  64
#define KC  4096

// ---------------- scratch (static device globals; no allocation) ----------------
__device__ float g_h1[(size_t)BB * HH];
__device__ float g_h2[(size_t)BB * HH];
__device__ float g_z [(size_t)BB * DE];
__device__ float g_ps[512 * HH];
__device__ float g_pq[512 * HH];
__device__ float g_ps2[16 * HH];
__device__ float g_pq2[16 * HH];
__device__ float g_scale[HH];
__device__ float g_shift[HH];
__device__ float g_c2[KC];
__device__ int   g_idx[BB];
__device__ uint32_t g_cb1[32 * 4096];        // codebook fp16-hi B-fragments (dist)
__device__ uint32_t g_cb2[32 * 4096];        // codebook fp16-lo
__device__ uint32_t g_af1h[4096 * 8 * 128];  // x A-fragments hi (K=128)
__device__ uint32_t g_af1l[4096 * 8 * 128];
__device__ uint32_t g_af2h[4096 * 16 * 128]; // bnrelu(h1) A-fragments hi (K=256)
__device__ uint32_t g_af2l[4096 * 16 * 128];
__device__ uint32_t g_w1h[32 * 8 * 64];      // W1 B-fragments
__device__ uint32_t g_w1l[32 * 8 * 64];
__device__ uint32_t g_w2h[32 * 16 * 64];     // W2 B-fragments
__device__ uint32_t g_w2l[32 * 16 * 64];

__device__ __forceinline__ uint32_t smem_u32(const void* p) {
    uint32_t a;
    asm("{ .reg .u64 t; cvta.to.shared.u64 t, %1; cvt.u32.u64 %0, t; }" : "=r"(a) : "l"(p));
    return a;
}
__device__ __forceinline__ void cp16(uint32_t dst, const void* src) {
    asm volatile("cp.async.cg.shared.global [%0], [%1], 16;" :: "r"(dst), "l"(src));
}
#define CP_COMMIT() asm volatile("cp.async.commit_group;" ::: "memory")
#define CP_WAIT0()  asm volatile("cp.async.wait_group 0;" ::: "memory")

__device__ __forceinline__ uint32_t packh2(float a, float b) {
    __half2 t = __floats2half2_rn(a, b);
    return *reinterpret_cast<uint32_t*>(&t);
}
__device__ __forceinline__ void split2(float a, float b, uint32_t& h, uint32_t& l) {
    h = packh2(a, b);
    const float ra = a - __half2float(__float2half_rn(a));
    const float rb = b - __half2float(__float2half_rn(b));
    l = packh2(ra, rb);
}
__device__ __forceinline__ void mma_f16(float c[4], uint32_t a0, uint32_t a1,
                                        uint32_t a2, uint32_t a3,
                                        uint32_t b0, uint32_t b1) {
    asm volatile(
        "mma.sync.aligned.m16n8k16.row.col.f32.f16.f16.f32 "
        "{%0,%1,%2,%3}, {%4,%5,%6,%7}, {%8,%9}, {%0,%1,%2,%3};"
        : "+f"(c[0]), "+f"(c[1]), "+f"(c[2]), "+f"(c[3])
        : "r"(a0), "r"(a1), "r"(a2), "r"(a3), "r"(b0), "r"(b1));
}

// ================= A-operand -> fp16 hi/lo fragments (m16n8k16 row A) =========
// thread = (mtg, ks, lane): computes uint4 {a0,a1,a2,a3} for its fragment slot.
template<int KST, bool BN>
__global__ void __launch_bounds__(256) cvt_a_kernel(
    const float* __restrict__ A, uint32_t* __restrict__ dh, uint32_t* __restrict__ dl)
{
    constexpr int K = KST * 16;
    constexpr int LK = (KST == 8) ? 3 : 4;
    const int gid = blockIdx.x * 256 + threadIdx.x;
    const int lane = gid & 31;
    const int ks = (gid >> 5) & (KST - 1);
    const int mtg = gid >> (5 + LK);

    const int r0 = mtg * 16 + (lane >> 2);
    const int kb = ks * 16 + 2 * (lane & 3);

    float2 v00 = *reinterpret_cast<const float2*>(A + (size_t)r0 * K + kb);
    float2 v02 = *reinterpret_cast<const float2*>(A + (size_t)r0 * K + kb + 8);
    float2 v10 = *reinterpret_cast<const float2*>(A + (size_t)(r0 + 8) * K + kb);
    float2 v12 = *reinterpret_cast<const float2*>(A + (size_t)(r0 + 8) * K + kb + 8);

    if (BN) {
        const float s0 = g_scale[kb],     t0 = g_shift[kb];
        const float s1 = g_scale[kb + 1], t1 = g_shift[kb + 1];
        const float s2 = g_scale[kb + 8], t2 = g_shift[kb + 8];
        const float s3 = g_scale[kb + 9], t3 = g_shift[kb + 9];
        v00.x = fmaxf(fmaf(v00.x, s0, t0), 0.f); v00.y = fmaxf(fmaf(v00.y, s1, t1), 0.f);
        v02.x = fmaxf(fmaf(v02.x, s2, t2), 0.f); v02.y = fmaxf(fmaf(v02.y, s3, t3), 0.f);
        v10.x = fmaxf(fmaf(v10.x, s0, t0), 0.f); v10.y = fmaxf(fmaf(v10.y, s1, t1), 0.f);
        v12.x = fmaxf(fmaf(v12.x, s2, t2), 0.f); v12.y = fmaxf(fmaf(v12.y, s3, t3), 0.f);
    }

    uint4 h, l;
    split2(v00.x, v00.y, h.x, l.x);
    split2(v10.x, v10.y, h.y, l.y);
    split2(v02.x, v02.y, h.z, l.z);
    split2(v12.x, v12.y, h.w, l.w);

    const size_t o = ((size_t)(mtg * KST + ks) * 32 + lane) * 4;
    *reinterpret_cast<uint4*>(dh + o) = h;
    *reinterpret_cast<uint4*>(dl + o) = l;
}

// ================= W -> fp16 hi/lo B-fragments (col B), N = 256 ===============
__global__ void __launch_bounds__(256) cvt_w_kernel(
    const float* __restrict__ W, uint32_t* __restrict__ dh, uint32_t* __restrict__ dl,
    int KST)
{
    const int gid = blockIdx.x * 256 + threadIdx.x;
    const int lane = gid & 31;
    const int ks = (gid >> 5) % KST;
    const int ntg = gid / (32 * KST);

    const int n = ntg * 8 + (lane >> 2);
    const int k0 = ks * 16 + 2 * (lane & 3);

    uint2 h, l;
    split2(W[(size_t)k0 * 256 + n],       W[(size_t)(k0 + 1) * 256 + n], h.x, l.x);
    split2(W[(size_t)(k0 + 8) * 256 + n], W[(size_t)(k0 + 9) * 256 + n], h.y, l.y);

    const size_t o = ((size_t)(ntg * KST + ks) * 32 + lane) * 2;
    *reinterpret_cast<uint2*>(dh + o) = h;
    *reinterpret_cast<uint2*>(dl + o) = l;
}

// ================= fp16 4-term split tensor GEMM, 128x128 CTA tile ============
// EPI: 0 = bias, 1 = bias+ReLU. BNACC: accumulate BN partial sums.
// smem byte offsets
#define HG_AH(b) ((b) * 32768)
#define HG_AL(b) (HG_AH(b) + 16384)
#define HG_BH(b) (65536 + (b) * 32768)
#define HG_BL(b) (HG_BH(b) + 16384)
#define HG_RED   131072
#define HG_SMEM(bnacc) (131072 + ((bnacc) ? 16384 : 0))

template<int KST>
__device__ __forceinline__ void hg_prefetch(
    uint32_t sb, int buf, int ck,
    const uint32_t* __restrict__ Ah, const uint32_t* __restrict__ Al,
    const uint32_t* __restrict__ Bh, const uint32_t* __restrict__ Bl,
    int mtg0, int ntg0, int tid)
{
    #pragma unroll
    for (int t = 0; t < 4; t++) {
        const int bi = t * 8 + (tid >> 5);
        const int mt = bi >> 2, ksl = bi & 3;
        const size_t gsrc = ((size_t)((mtg0 + mt) * KST + ck * 4 + ksl)) * 128 + (tid & 31) * 4;
        const uint32_t doff = (uint32_t)(((mt * 4 + ksl) * 128 + (tid & 31) * 4) << 2);
        cp16(sb + HG_AH(buf) + doff, Ah + gsrc);
        cp16(sb + HG_AL(buf) + doff, Al + gsrc);
    }
    #pragma unroll
    for (int t = 0; t < 4; t++) {
        const int bi = t * 16 + (tid >> 4);
        const int nt = bi >> 2, ksl = bi & 3;
        const size_t gsrc = ((size_t)((ntg0 + nt) * KST + ck * 4 + ksl)) * 64 + (tid & 15) * 4;
        const uint32_t doff = (uint32_t)(((nt * 4 + ksl) * 64 + (tid & 15) * 4) << 2);
        cp16(sb + HG_BH(buf) + doff, Bh + gsrc);
        cp16(sb + HG_BL(buf) + doff, Bl + gsrc);
    }
    CP_COMMIT();
}

template<int KST, int EPI, bool BNACC>
__global__ void __launch_bounds__(256, 1) hgemm_kernel(
    const uint32_t* __restrict__ Ah, const uint32_t* __restrict__ Al,
    const uint32_t* __restrict__ Bh, const uint32_t* __restrict__ Bl,
    const float* __restrict__ bias, float* __restrict__ C,
    float* __restrict__ ps, float* __restrict__ pq)
{
    extern __shared__ char smem[];
    const uint32_t sb = smem_u32(smem);
    constexpr int NCH = KST / 4;

    const int tid  = threadIdx.x;
    const int lane = tid & 31;
    const int wid  = tid >> 5;
    const int wr   = wid >> 2;
    const int wc   = wid & 3;
    const int mtg0 = blockIdx.y * 8;
    const int ntg0 = blockIdx.x * 16;

    hg_prefetch<KST>(sb, 0, 0, Ah, Al, Bh, Bl, mtg0, ntg0, tid);

    float acc[4][4][4];
    #pragma unroll
    for (int mt = 0; mt < 4; mt++)
        #pragma unroll
        for (int nt = 0; nt < 4; nt++)
            #pragma unroll
            for (int j = 0; j < 4; j++) acc[mt][nt][j] = 0.f;

    for (int ck = 0; ck < NCH; ck++) {
        const int buf = ck & 1;
        CP_WAIT0();
        __syncthreads();
        if (ck + 1 < NCH)
            hg_prefetch<KST>(sb, buf ^ 1, ck + 1, Ah, Al, Bh, Bl, mtg0, ntg0, tid);

        const uint32_t* sAh = (const uint32_t*)(smem + HG_AH(buf));
        const uint32_t* sAl = (const uint32_t*)(smem + HG_AL(buf));
        const uint32_t* sBh = (const uint32_t*)(smem + HG_BH(buf));
        const uint32_t* sBl = (const uint32_t*)(smem + HG_BL(buf));

        #pragma unroll
        for (int ks = 0; ks < 4; ks++) {
            uint4 a1[4], a2[4];
            uint2 b1[4], b2[4];
            #pragma unroll
            for (int mt = 0; mt < 4; mt++) {
                const int o = (((wr * 4 + mt) * 4 + ks) * 32 + lane) * 4;
                a1[mt] = *reinterpret_cast<const uint4*>(sAh + o);
                a2[mt] = *reinterpret_cast<const uint4*>(sAl + o);
            }
            #pragma unroll
            for (int nt = 0; nt < 4; nt++) {
                const int o = (((wc * 4 + nt) * 4 + ks) * 32 + lane) * 2;
                b1[nt] = *reinterpret_cast<const uint2*>(sBh + o);
                b2[nt] = *reinterpret_cast<const uint2*>(sBl + o);
            }
            #pragma unroll
            for (int mt = 0; mt < 4; mt++)
                #pragma unroll
                for (int nt = 0; nt < 4; nt++)
                    mma_f16(acc[mt][nt], a1[mt].x, a1[mt].y, a1[mt].z, a1[mt].w,
                            b1[nt].x, b1[nt].y);
            #pragma unroll
            for (int mt = 0; mt < 4; mt++)
                #pragma unroll
                for (int nt = 0; nt < 4; nt++)
                    mma_f16(acc[mt][nt], a1[mt].x, a1[mt].y, a1[mt].z, a1[mt].w,
                            b2[nt].x, b2[nt].y);
            #pragma unroll
            for (int mt = 0; mt < 4; mt++)
                #pragma unroll
                for (int nt = 0; nt < 4; nt++)
                    mma_f16(acc[mt][nt], a2[mt].x, a2[mt].y, a2[mt].z, a2[mt].w,
                            b1[nt].x, b1[nt].y);
            #pragma unroll
            for (int mt = 0; mt < 4; mt++)
                #pragma unroll
                for (int nt = 0; nt < 4; nt++)
                    mma_f16(acc[mt][nt], a2[mt].x, a2[mt].y, a2[mt].z, a2[mt].w,
                            b2[nt].x, b2[nt].y);
        }
        __syncthreads();
    }

    // ---- epilogue ----
    float cs[8], cq[8];
    if (BNACC) {
        #pragma unroll
        for (int j = 0; j < 8; j++) { cs[j] = 0.f; cq[j] = 0.f; }
    }

    #pragma unroll
    for (int nt = 0; nt < 4; nt++) {
        const int c0 = blockIdx.x * 128 + wc * 32 + nt * 8 + 2 * (lane & 3);
        const float bv0 = bias[c0], bv1 = bias[c0 + 1];
        #pragma unroll
        for (int mt = 0; mt < 4; mt++) {
            const int r = blockIdx.y * 128 + wr * 64 + mt * 16 + (lane >> 2);
            float v0 = acc[mt][nt][0] + bv0;
            float v1 = acc[mt][nt][1] + bv1;
            float v2 = acc[mt][nt][2] + bv0;
            float v3 = acc[mt][nt][3] + bv1;
            if (EPI == 1) {
                v0 = fmaxf(v0, 0.f); v1 = fmaxf(v1, 0.f);
                v2 = fmaxf(v2, 0.f); v3 = fmaxf(v3, 0.f);
            }
            *reinterpret_cast<float2*>(C + (size_t)r * HH + c0)       = make_float2(v0, v1);
            *reinterpret_cast<float2*>(C + (size_t)(r + 8) * HH + c0) = make_float2(v2, v3);
            if (BNACC) {
                cs[nt * 2 + 0] += v0 + v2;
                cs[nt * 2 + 1] += v1 + v3;
                cq[nt * 2 + 0] = fmaf(v0, v0, fmaf(v2, v2, cq[nt * 2 + 0]));
                cq[nt * 2 + 1] = fmaf(v1, v1, fmaf(v3, v3, cq[nt * 2 + 1]));
            }
        }
    }

    if (BNACC) {
        float* red = (float*)(smem + HG_RED);
        const int slot = wr * 8 + (lane >> 2);
        #pragma unroll
        for (int nt = 0; nt < 4; nt++) {
            #pragma unroll
            for (int h = 0; h < 2; h++) {
                const int cl = wc * 32 + nt * 8 + 2 * (lane & 3) + h;
                red[cl * 16 + slot]        = cs[nt * 2 + h];
                red[2048 + cl * 16 + slot] = cq[nt * 2 + h];
            }
        }
        __syncthreads();
        if (tid < 128) {
            float s = 0.f, q = 0.f;
            #pragma unroll
            for (int t = 0; t < 16; t++) {
                s += red[tid * 16 + t];
                q += red[2048 + tid * 16 + t];
            }
            ps[(size_t)blockIdx.y * HH + blockIdx.x * 128 + tid] = s;
            pq[(size_t)blockIdx.y * HH + blockIdx.x * 128 + tid] = q;
        }
    }
}

// ================= GEMM3: 128x64 tile, tanh epilogue (known-good fp32) =========
__global__ void __launch_bounds__(256, 2) sgemm_z_kernel(
    const float* __restrict__ A, const float* __restrict__ Bm,
    const float* __restrict__ bias, float* __restrict__ C, int K)
{
    __shared__ float As[2][8][128];
    __shared__ float Bs[2][8][68];

    const int tid = threadIdx.x;
    const int tx = tid & 7, ty = tid >> 3;
    const int m0 = blockIdx.x * 128;
    const int ar = tid >> 1, ac = (tid & 1) * 4;
    const int br = tid >> 5, bc = (tid & 31) * 2;

    {
        float4 av = *reinterpret_cast<const float4*>(A + (size_t)(m0 + ar) * K + ac);
        float2 bv = *reinterpret_cast<const float2*>(Bm + (size_t)br * DE + bc);
        As[0][ac + 0][ar] = av.x;
        As[0][ac + 1][ar] = av.y;
        As[0][ac + 2][ar] = av.z;
        As[0][ac + 3][ar] = av.w;
        *reinterpret_cast<float2*>(&Bs[0][br][bc]) = bv;
    }
    __syncthreads();

    float acc[4][8] = {};
    int buf = 0;

    for (int k0 = 8; k0 <= K; k0 += 8) {
        const bool has = (k0 < K);
        float4 av_n;
        float2 bv_n;
        if (has) {
            av_n = *reinterpret_cast<const float4*>(A + (size_t)(m0 + ar) * K + (k0 + ac));
            bv_n = *reinterpret_cast<const float2*>(Bm + (size_t)(k0 + br) * DE + bc);
        }
        #pragma unroll
        for (int kk = 0; kk < 8; kk++) {
            float a[4], b[8];
            *reinterpret_cast<float4*>(&a[0]) = *reinterpret_cast<const float4*>(&As[buf][kk][ty * 4]);
            *reinterpret_cast<float4*>(&b[0]) = *reinterpret_cast<const float4*>(&Bs[buf][kk][tx * 8 + 0]);
            *reinterpret_cast<float4*>(&b[4]) = *reinterpret_cast<const float4*>(&Bs[buf][kk][tx * 8 + 4]);
            #pragma unroll
            for (int i = 0; i < 4; i++)
                #pragma unroll
                for (int j = 0; j < 8; j++)
                    acc[i][j] = fmaf(a[i], b[j], acc[i][j]);
        }
        if (has) {
            As[buf ^ 1][ac + 0][ar] = av_n.x;
            As[buf ^ 1][ac + 1][ar] = av_n.y;
            As[buf ^ 1][ac + 2][ar] = av_n.z;
            As[buf ^ 1][ac + 3][ar] = av_n.w;
            *reinterpret_cast<float2*>(&Bs[buf ^ 1][br][bc]) = bv_n;
            __syncthreads();
            buf ^= 1;
        }
    }

    #pragma unroll
    for (int i = 0; i < 4; i++) {
        const int m = m0 + ty * 4 + i;
        #pragma unroll
        for (int j = 0; j < 8; j++) {
            const int n = tx * 8 + j;
            C[(size_t)m * DE + n] = tanhf(acc[i][j] + bias[n]);
        }
    }
}

// ---------------- BN finalize: parallel two-stage -----------------
__global__ void bn_stage1_kernel()
{
    const int j = threadIdx.x;
    const int b0 = blockIdx.x * 32;
    float s = 0.f, q = 0.f;
    #pragma unroll 8
    for (int r = 0; r < 32; r++) {
        s += g_ps[(size_t)(b0 + r) * HH + j];
        q += g_pq[(size_t)(b0 + r) * HH + j];
    }
    g_ps2[blockIdx.x * HH + j] = s;
    g_pq2[blockIdx.x * HH + j] = q;
}

__global__ void bn_stage2_kernel(const float* __restrict__ gamma,
                                 const float* __restrict__ beta)
{
    const int j = threadIdx.x;
    float s = 0.f, q = 0.f;
    #pragma unroll
    for (int b = 0; b < 16; b++) { s += g_ps2[b * HH + j]; q += g_pq2[b * HH + j]; }
    const float mean = s * (1.f / (float)BB);
    const float var  = q * (1.f / (float)BB) - mean * mean;
    const float inv  = rsqrtf(var + 1e-5f);
    const float sc   = gamma[j] * inv;
    g_scale[j] = sc;
    g_shift[j] = beta[j] - mean * sc;
}

// ---------------- codebook squared norms -----------------
__global__ void c2_kernel(const float* __restrict__ cb)
{
    const int k = blockIdx.x * 256 + threadIdx.x;
    if (k < KC) {
        float s = 0.f;
        #pragma unroll
        for (int j = 0; j < DE; j++) {
            float v = cb[(size_t)k * DE + j];
            s = fmaf(v, v, s);
        }
        g_c2[k] = s;
    }
}

// ---------------- codebook -> fp16 hi/lo B-fragments (dist, per chunk) ---------
__global__ void cvt_cb_kernel(const float* __restrict__ cb)
{
    const int ch = blockIdx.x;
    const int tid = threadIdx.x;
    const float* src = cb + (size_t)ch * 8192;
    #pragma unroll
    for (int t = 0; t < 16; t++) {
        const int lin = t * 256 + tid;
        const int n = lin >> 5, k2 = lin & 31;
        const float2 v = *reinterpret_cast<const float2*>(src + n * 64 + 2 * k2);
        uint32_t h, l;
        split2(v.x, v.y, h, l);
        const int nt = n >> 3, nn = n & 7;
        const int ks = k2 >> 3, kk2 = k2 & 7;
        const int o = ((nt * 4 + ks) * 32 + nn * 4 + (kk2 & 3)) * 2 + (kk2 >> 2);
        g_cb1[ch * 4096 + o] = h;
        g_cb2[ch * 4096 + o] = l;
    }
}

// ================= mma.sync fp16 3-term split dist + argmin (known-good R7) =====
#define D_A1   0
#define D_A2   16384
#define D_B1(buf) (32768 + (buf) * 32768)
#define D_B2(buf) (D_B1(buf) + 16384)
#define D_C2   98304
#define D_REDF 99328
#define D_REDI 107520
#define D_SMEM 115712

__global__ void __launch_bounds__(256, 1) dist_argmin_mma(
    const float* __restrict__ z, int* __restrict__ idxo)
{
    extern __shared__ char smem[];
    const uint32_t sb = smem_u32(smem);
    uint32_t* sA1 = (uint32_t*)(smem + D_A1);
    uint32_t* sA2 = (uint32_t*)(smem + D_A2);
    float*    c2s = (float*)(smem + D_C2);
    float*    redF = (float*)(smem + D_REDF);
    int*      redI = (int*)(smem + D_REDI);

    const int tid  = threadIdx.x;
    const int lane = tid & 31;
    const int wid  = tid >> 5;
    const int wr   = wid >> 2;
    const int wc   = wid & 3;
    const int row0 = blockIdx.x * 128;

    {
        const uint4* g1 = (const uint4*)(g_cb1);
        const uint4* g2 = (const uint4*)(g_cb2);
        const uint32_t b1 = sb + D_B1(0);
        const uint32_t b2 = sb + D_B2(0);
        #pragma unroll
        for (int t = 0; t < 4; t++) {
            cp16(b1 + (t * 256 + tid) * 16, g1 + t * 256 + tid);
            cp16(b2 + (t * 256 + tid) * 16, g2 + t * 256 + tid);
        }
        if (tid < 32) cp16(sb + D_C2 + tid * 16, (const uint4*)g_c2 + tid);
        CP_COMMIT();
    }

    #pragma unroll
    for (int t = 0; t < 16; t++) {
        const int lin = t * 256 + tid;
        const int r = lin >> 5, k2 = lin & 31;
        const float2 v = *reinterpret_cast<const float2*>(z + (size_t)(row0 + r) * DE + 2 * k2);
        uint32_t h, l;
        split2(v.x, v.y, h, l);
        const int mt = r >> 4, rr = r & 15;
        const int ks = k2 >> 3, kk2 = k2 & 7;
        const int ln = (rr & 7) * 4 + (kk2 & 3);
        const int rg = (rr >> 3) + 2 * (kk2 >> 2);
        const int o = ((mt * 4 + ks) * 32 + ln) * 4 + rg;
        sA1[o] = h;
        sA2[o] = l;
    }

    float bestv[8];
    int   besti[8];
    #pragma unroll
    for (int s = 0; s < 8; s++) { bestv[s] = 3.4e38f; besti[s] = 0; }

    for (int ch = 0; ch < 32; ch++) {
        const int buf = ch & 1;
        CP_WAIT0();
        __syncthreads();

        if (ch + 1 < 32) {
            const uint4* g1 = (const uint4*)(g_cb1 + (ch + 1) * 4096);
            const uint4* g2 = (const uint4*)(g_cb2 + (ch + 1) * 4096);
            const uint32_t b1 = sb + D_B1(buf ^ 1);
            const uint32_t b2 = sb + D_B2(buf ^ 1);
            #pragma unroll
            for (int t = 0; t < 4; t++) {
                cp16(b1 + (t * 256 + tid) * 16, g1 + t * 256 + tid);
                cp16(b2 + (t * 256 + tid) * 16, g2 + t * 256 + tid);
            }
            if (tid < 32)
                cp16(sb + D_C2 + (buf ^ 1) * 512 + tid * 16,
                     (const uint4*)(g_c2 + (ch + 1) * 128) + tid);
            CP_COMMIT();
        }

        const uint32_t* sB1 = (const uint32_t*)(smem + D_B1(buf));
        const uint32_t* sB2 = (const uint32_t*)(smem + D_B2(buf));

        float acc[4][4][4];
        #pragma unroll
        for (int mt = 0; mt < 4; mt++)
            #pragma unroll
            for (int nt = 0; nt < 4; nt++)
                #pragma unroll
                for (int j = 0; j < 4; j++) acc[mt][nt][j] = 0.f;

        #pragma unroll
        for (int ks = 0; ks < 4; ks++) {
            uint4 a1[4], a2[4];
            uint2 b1[4], b2[4];
            #pragma unroll
            for (int mt = 0; mt < 4; mt++) {
                const int o = (((wr * 4 + mt) * 4 + ks) * 32 + lane) * 4;
                a1[mt] = *reinterpret_cast<const uint4*>(sA1 + o);
                a2[mt] = *reinterpret_cast<const uint4*>(sA2 + o);
            }
            #pragma unroll
            for (int nt = 0; nt < 4; nt++) {
                const int o = (((wc * 4 + nt) * 4 + ks) * 32 + lane) * 2;
                b1[nt] = *reinterpret_cast<const uint2*>(sB1 + o);
                b2[nt] = *reinterpret_cast<const uint2*>(sB2 + o);
            }
            #pragma unroll
            for (int mt = 0; mt < 4; mt++)
                #pragma unroll
                for (int nt = 0; nt < 4; nt++)
                    mma_f16(acc[mt][nt], a1[mt].x, a1[mt].y, a1[mt].z, a1[mt].w,
                            b1[nt].x, b1[nt].y);
            #pragma unroll
            for (int mt = 0; mt < 4; mt++)
                #pragma unroll
                for (int nt = 0; nt < 4; nt++)
                    mma_f16(acc[mt][nt], a1[mt].x, a1[mt].y, a1[mt].z, a1[mt].w,
                            b2[nt].x, b2[nt].y);
            #pragma unroll
            for (int mt = 0; mt < 4; mt++)
                #pragma unroll
                for (int nt = 0; nt < 4; nt++)
                    mma_f16(acc[mt][nt], a2[mt].x, a2[mt].y, a2[mt].z, a2[mt].w,
                            b1[nt].x, b1[nt].y);
        }

        const float* c2p = c2s + buf * 128;
        #pragma unroll
        for (int nt = 0; nt < 4; nt++) {
            const int ncol = wc * 32 + nt * 8 + 2 * (lane & 3);
            const float cc0 = c2p[ncol];
            const float cc1 = c2p[ncol + 1];
            const int gi = ch * 128 + ncol;
            #pragma unroll
            for (int mt = 0; mt < 4; mt++) {
                const float d0 = fmaf(-2.f, acc[mt][nt][0], cc0);
                const float d1 = fmaf(-2.f, acc[mt][nt][1], cc1);
                const float d2 = fmaf(-2.f, acc[mt][nt][2], cc0);
                const float d3 = fmaf(-2.f, acc[mt][nt][3], cc1);
                const int s0 = mt * 2, s1 = mt * 2 + 1;
                if (d0 < bestv[s0]) { bestv[s0] = d0; besti[s0] = gi; }
                if (d1 < bestv[s0]) { bestv[s0] = d1; besti[s0] = gi + 1; }
                if (d2 < bestv[s1]) { bestv[s1] = d2; besti[s1] = gi; }
                if (d3 < bestv[s1]) { bestv[s1] = d3; besti[s1] = gi + 1; }
            }
        }
        __syncthreads();
    }

    #pragma unroll
    for (int s = 0; s < 8; s++) {
        const int mt = s >> 1, half = s & 1;
        const int row = wr * 64 + mt * 16 + half * 8 + (lane >> 2);
        const int e = wc * 4 + (lane & 3);
        redF[row * 16 + e] = bestv[s];
        redI[row * 16 + e] = besti[s];
    }
    __syncthreads();
    if (tid < 128) {
        float bs = 3.4e38f;
        int   b  = 0x7fffffff;
        #pragma unroll
        for (int e = 0; e < 16; e++) {
            const float sv = redF[tid * 16 + e];
            const int   iv = redI[tid * 16 + e];
            if (sv < bs || (sv == bs && iv < b)) { bs = sv; b = iv; }
        }
        idxo[row0 + tid] = b;
    }
}

// ---------------- output writer ----------------
__global__ void writeout_kernel(const float* __restrict__ cb,
                                float* __restrict__ outf, int* __restrict__ outi,
                                int mode)
{
    const int gid = blockIdx.x * 256 + threadIdx.x;
    const int row = gid >> 6, j = gid & 63;
    const int id = g_idx[row];
    if (mode == 0) {
        if (j == 0) outf[row] = (float)id;
        outf[BB + gid] = cb[(size_t)id * DE + j];
    } else if (mode == 1) {
        outf[gid] = cb[(size_t)id * DE + j];
    } else {
        if (j == 0) outi[row] = id;
    }
}

// ---------------- launch -----------------------------------------------------------
extern "C" void kernel_launch(void* const* d_in, const int* in_sizes, int n_in,
                              void* d_out, int out_size)
{
    const float* x     = (const float*)d_in[0];
    const float* W1    = (const float*)d_in[1];
    const float* b1    = (const float*)d_in[2];
    const float* gamma = (const float*)d_in[3];
    const float* beta  = (const float*)d_in[4];
    const float* W2    = (const float*)d_in[5];
    const float* b2    = (const float*)d_in[6];
    const float* W3    = (const float*)d_in[7];
    const float* b3    = (const float*)d_in[8];
    const float* cb    = (const float*)d_in[9];

    float *h1p = nullptr, *h2p = nullptr, *zp = nullptr, *psp = nullptr, *pqp = nullptr;
    int *idxp = nullptr;
    uint32_t *a1h = nullptr, *a1l = nullptr, *a2h = nullptr, *a2l = nullptr;
    uint32_t *w1h = nullptr, *w1l = nullptr, *w2h = nullptr, *w2l = nullptr;
    cudaGetSymbolAddress((void**)&h1p, g_h1);
    cudaGetSymbolAddress((void**)&h2p, g_h2);
    cudaGetSymbolAddress((void**)&zp,  g_z);
    cudaGetSymbolAddress((void**)&psp, g_ps);
    cudaGetSymbolAddress((void**)&pqp, g_pq);
    cudaGetSymbolAddress((void**)&idxp, g_idx);
    cudaGetSymbolAddress((void**)&a1h, g_af1h);
    cudaGetSymbolAddress((void**)&a1l, g_af1l);
    cudaGetSymbolAddress((void**)&a2h, g_af2h);
    cudaGetSymbolAddress((void**)&a2l, g_af2l);
    cudaGetSymbolAddress((void**)&w1h, g_w1h);
    cudaGetSymbolAddress((void**)&w1l, g_w1l);
    cudaGetSymbolAddress((void**)&w2h, g_w2h);
    cudaGetSymbolAddress((void**)&w2l, g_w2l);

    cudaFuncSetAttribute(dist_argmin_mma, cudaFuncAttributeMaxDynamicSharedMemorySize, D_SMEM);
    cudaFuncSetAttribute(hgemm_kernel<8, 0, true>,
                         cudaFuncAttributeMaxDynamicSharedMemorySize, HG_SMEM(true));
    cudaFuncSetAttribute(hgemm_kernel<16, 1, false>,
                         cudaFuncAttributeMaxDynamicSharedMemorySize, HG_SMEM(false));

    dim3 blk(256);

    // prep: operand conversions (x, W1, W2, codebook) + codebook norms
    cvt_a_kernel<8, false><<<4096, blk>>>(x, a1h, a1l);
    cvt_w_kernel<<<32, blk>>>(W1, w1h, w1l, 8);
    cvt_w_kernel<<<64, blk>>>(W2, w2h, w2l, 16);
    c2_kernel<<<KC / 256, blk>>>(cb);
    cvt_cb_kernel<<<32, blk>>>(cb);

    // h1 = x @ W1 + b1 (fp16 4-term tensor), fused BN partial sums
    hgemm_kernel<8, 0, true><<<dim3(2, BB / 128), blk, HG_SMEM(true)>>>(
        a1h, a1l, w1h, w1l, b1, h1p, psp, pqp);

    // BN finalize
    bn_stage1_kernel<<<16, HH>>>();
    bn_stage2_kernel<<<1, HH>>>(gamma, beta);

    // bnrelu(h1) -> A fragments
    cvt_a_kernel<16, true><<<8192, blk>>>(h1p, a2h, a2l);

    // h2 = relu( bnrelu(h1) @ W2 + b2 ) (fp16 4-term tensor)
    hgemm_kernel<16, 1, false><<<dim3(2, BB / 128), blk, HG_SMEM(false)>>>(
        a2h, a2l, w2h, w2l, b2, h2p, nullptr, nullptr);

    // z = tanh( h2 @ W3 + b3 ) (fp32)
    sgemm_z_kernel<<<BB / 128, blk>>>(h2p, W3, b3, zp, HH);

    // dist/argmin (fp16 3-term split)
    dist_argmin_mma<<<BB / 128, blk, D_SMEM>>>(zp, idxp);

    // outputs
    int mode;
    if      (out_size == BB * (DE + 1)) mode = 0;
    else if (out_size == BB * DE)       mode = 1;
    else                                mode = 2;
    writeout_kernel<<<(BB * DE) / 256, blk>>>(cb, (float*)d_out, (int*)d_out, mode);
}

// round 9
// speedup vs baseline: 2.8351x; 1.1573x over previous
#include <cuda_runtime.h>
#include <cuda_fp16.h>
#include <math.h>
#include <stdint.h>

#define BB  65536
#define DIN 128
#define HH  256
#define DE  64
#define KC  4096

// ---------------- scratch (static device globals; no allocation) ----------------
__device__ float g_h1[(size_t)BB * HH];
__device__ float g_ps[512 * HH];
__device__ float g_pq[512 * HH];
__device__ float g_ps2[16 * HH];
__device__ float g_pq2[16 * HH];
__device__ float g_scale[HH];
__device__ float g_shift[HH];
__device__ float g_c2[KC];
__device__ int   g_idx[BB];
__device__ uint32_t g_cb1[32 * 4096];        // codebook fp16-hi B-fragments (dist)
__device__ uint32_t g_cb2[32 * 4096];        // codebook fp16-lo
__device__ uint32_t g_af1h[4096 * 8 * 128];  // x A-fragments hi (K=128)
__device__ uint32_t g_af1l[4096 * 8 * 128];
__device__ uint32_t g_af2h[4096 * 16 * 128]; // bnrelu(h1) A-fragments (K=256)
__device__ uint32_t g_af2l[4096 * 16 * 128];
__device__ uint32_t g_af3h[4096 * 16 * 128]; // h2 A-fragments (K=256), from hgemm2
__device__ uint32_t g_af3l[4096 * 16 * 128];
__device__ uint32_t g_zfh[4096 * 4 * 128];   // z A-fragments (K=64), from hgemm3
__device__ uint32_t g_zfl[4096 * 4 * 128];
__device__ uint32_t g_w1h[32 * 8 * 64];      // W1 B-fragments
__device__ uint32_t g_w1l[32 * 8 * 64];
__device__ uint32_t g_w2h[32 * 16 * 64];     // W2 B-fragments
__device__ uint32_t g_w2l[32 * 16 * 64];
__device__ uint32_t g_w3h[8 * 16 * 64];      // W3 B-fragments (N=64)
__device__ uint32_t g_w3l[8 * 16 * 64];

__device__ __forceinline__ uint32_t smem_u32(const void* p) {
    uint32_t a;
    asm("{ .reg .u64 t; cvta.to.shared.u64 t, %1; cvt.u32.u64 %0, t; }" : "=r"(a) : "l"(p));
    return a;
}
__device__ __forceinline__ void cp16(uint32_t dst, const void* src) {
    asm volatile("cp.async.cg.shared.global [%0], [%1], 16;" :: "r"(dst), "l"(src));
}
#define CP_COMMIT() asm volatile("cp.async.commit_group;" ::: "memory")
#define CP_WAIT0()  asm volatile("cp.async.wait_group 0;" ::: "memory")

__device__ __forceinline__ uint32_t packh2(float a, float b) {
    __half2 t = __floats2half2_rn(a, b);
    return *reinterpret_cast<uint32_t*>(&t);
}
__device__ __forceinline__ void split2(float a, float b, uint32_t& h, uint32_t& l) {
    h = packh2(a, b);
    const float ra = a - __half2float(__float2half_rn(a));
    const float rb = b - __half2float(__float2half_rn(b));
    l = packh2(ra, rb);
}
__device__ __forceinline__ void mma_f16(float c[4], uint32_t a0, uint32_t a1,
                                        uint32_t a2, uint32_t a3,
                                        uint32_t b0, uint32_t b1) {
    asm volatile(
        "mma.sync.aligned.m16n8k16.row.col.f32.f16.f16.f32 "
        "{%0,%1,%2,%3}, {%4,%5,%6,%7}, {%8,%9}, {%0,%1,%2,%3};"
        : "+f"(c[0]), "+f"(c[1]), "+f"(c[2]), "+f"(c[3])
        : "r"(a0), "r"(a1), "r"(a2), "r"(a3), "r"(b0), "r"(b1));
}

// ================= A-operand -> fp16 hi/lo fragments (m16n8k16 row A) =========
template<int KST, bool BN>
__global__ void __launch_bounds__(256) cvt_a_kernel(
    const float* __restrict__ A, uint32_t* __restrict__ dh, uint32_t* __restrict__ dl)
{
    constexpr int K = KST * 16;
    constexpr int LK = (KST == 8) ? 3 : 4;
    const int gid = blockIdx.x * 256 + threadIdx.x;
    const int lane = gid & 31;
    const int ks = (gid >> 5) & (KST - 1);
    const int mtg = gid >> (5 + LK);

    const int r0 = mtg * 16 + (lane >> 2);
    const int kb = ks * 16 + 2 * (lane & 3);

    float2 v00 = *reinterpret_cast<const float2*>(A + (size_t)r0 * K + kb);
    float2 v02 = *reinterpret_cast<const float2*>(A + (size_t)r0 * K + kb + 8);
    float2 v10 = *reinterpret_cast<const float2*>(A + (size_t)(r0 + 8) * K + kb);
    float2 v12 = *reinterpret_cast<const float2*>(A + (size_t)(r0 + 8) * K + kb + 8);

    if (BN) {
        const float s0 = g_scale[kb],     t0 = g_shift[kb];
        const float s1 = g_scale[kb + 1], t1 = g_shift[kb + 1];
        const float s2 = g_scale[kb + 8], t2 = g_shift[kb + 8];
        const float s3 = g_scale[kb + 9], t3 = g_shift[kb + 9];
        v00.x = fmaxf(fmaf(v00.x, s0, t0), 0.f); v00.y = fmaxf(fmaf(v00.y, s1, t1), 0.f);
        v02.x = fmaxf(fmaf(v02.x, s2, t2), 0.f); v02.y = fmaxf(fmaf(v02.y, s3, t3), 0.f);
        v10.x = fmaxf(fmaf(v10.x, s0, t0), 0.f); v10.y = fmaxf(fmaf(v10.y, s1, t1), 0.f);
        v12.x = fmaxf(fmaf(v12.x, s2, t2), 0.f); v12.y = fmaxf(fmaf(v12.y, s3, t3), 0.f);
    }

    uint4 h, l;
    split2(v00.x, v00.y, h.x, l.x);
    split2(v10.x, v10.y, h.y, l.y);
    split2(v02.x, v02.y, h.z, l.z);
    split2(v12.x, v12.y, h.w, l.w);

    const size_t o = ((size_t)(mtg * KST + ks) * 32 + lane) * 4;
    *reinterpret_cast<uint4*>(dh + o) = h;
    *reinterpret_cast<uint4*>(dl + o) = l;
}

// ================= W -> fp16 hi/lo B-fragments (col B) ========================
__global__ void __launch_bounds__(256) cvt_w_kernel(
    const float* __restrict__ W, uint32_t* __restrict__ dh, uint32_t* __restrict__ dl,
    int KST, int N)
{
    const int gid = blockIdx.x * 256 + threadIdx.x;
    const int lane = gid & 31;
    const int ks = (gid >> 5) % KST;
    const int ntg = gid / (32 * KST);

    const int n = ntg * 8 + (lane >> 2);
    const int k0 = ks * 16 + 2 * (lane & 3);

    uint2 h, l;
    split2(W[(size_t)k0 * N + n],       W[(size_t)(k0 + 1) * N + n], h.x, l.x);
    split2(W[(size_t)(k0 + 8) * N + n], W[(size_t)(k0 + 9) * N + n], h.y, l.y);

    const size_t o = ((size_t)(ntg * KST + ks) * 32 + lane) * 2;
    *reinterpret_cast<uint2*>(dh + o) = h;
    *reinterpret_cast<uint2*>(dl + o) = l;
}

// ================= fp16 4-term split tensor GEMM, 128x128 CTA tile ============
#define HG_AH(b) ((b) * 32768)
#define HG_AL(b) (HG_AH(b) + 16384)
#define HG_BH(b) (65536 + (b) * 32768)
#define HG_BL(b) (HG_BH(b) + 16384)
#define HG_RED   131072
#define HG_SMEM(bnacc) (131072 + ((bnacc) ? 16384 : 0))

template<int KST>
__device__ __forceinline__ void hg_prefetch(
    uint32_t sb, int buf, int ck,
    const uint32_t* __restrict__ Ah, const uint32_t* __restrict__ Al,
    const uint32_t* __restrict__ Bh, const uint32_t* __restrict__ Bl,
    int mtg0, int ntg0, int tid)
{
    #pragma unroll
    for (int t = 0; t < 4; t++) {
        const int bi = t * 8 + (tid >> 5);
        const int mt = bi >> 2, ksl = bi & 3;
        const size_t gsrc = ((size_t)((mtg0 + mt) * KST + ck * 4 + ksl)) * 128 + (tid & 31) * 4;
        const uint32_t doff = (uint32_t)(((mt * 4 + ksl) * 128 + (tid & 31) * 4) << 2);
        cp16(sb + HG_AH(buf) + doff, Ah + gsrc);
        cp16(sb + HG_AL(buf) + doff, Al + gsrc);
    }
    #pragma unroll
    for (int t = 0; t < 4; t++) {
        const int bi = t * 16 + (tid >> 4);
        const int nt = bi >> 2, ksl = bi & 3;
        const size_t gsrc = ((size_t)((ntg0 + nt) * KST + ck * 4 + ksl)) * 64 + (tid & 15) * 4;
        const uint32_t doff = (uint32_t)(((nt * 4 + ksl) * 64 + (tid & 15) * 4) << 2);
        cp16(sb + HG_BH(buf) + doff, Bh + gsrc);
        cp16(sb + HG_BL(buf) + doff, Bl + gsrc);
    }
    CP_COMMIT();
}

template<int KST, int EPI, bool BNACC, bool FRAGOUT>
__global__ void __launch_bounds__(256, 1) hgemm_kernel(
    const uint32_t* __restrict__ Ah, const uint32_t* __restrict__ Al,
    const uint32_t* __restrict__ Bh, const uint32_t* __restrict__ Bl,
    const float* __restrict__ bias, float* __restrict__ C,
    float* __restrict__ ps, float* __restrict__ pq,
    uint32_t* __restrict__ dh, uint32_t* __restrict__ dl)
{
    extern __shared__ char smem[];
    const uint32_t sb = smem_u32(smem);
    constexpr int NCH = KST / 4;

    const int tid  = threadIdx.x;
    const int lane = tid & 31;
    const int wid  = tid >> 5;
    const int wr   = wid >> 2;
    const int wc   = wid & 3;
    const int mtg0 = blockIdx.y * 8;
    const int ntg0 = blockIdx.x * 16;

    hg_prefetch<KST>(sb, 0, 0, Ah, Al, Bh, Bl, mtg0, ntg0, tid);

    float acc[4][4][4];
    #pragma unroll
    for (int mt = 0; mt < 4; mt++)
        #pragma unroll
        for (int nt = 0; nt < 4; nt++)
            #pragma unroll
            for (int j = 0; j < 4; j++) acc[mt][nt][j] = 0.f;

    for (int ck = 0; ck < NCH; ck++) {
        const int buf = ck & 1;
        CP_WAIT0();
        __syncthreads();
        if (ck + 1 < NCH)
            hg_prefetch<KST>(sb, buf ^ 1, ck + 1, Ah, Al, Bh, Bl, mtg0, ntg0, tid);

        const uint32_t* sAh = (const uint32_t*)(smem + HG_AH(buf));
        const uint32_t* sAl = (const uint32_t*)(smem + HG_AL(buf));
        const uint32_t* sBh = (const uint32_t*)(smem + HG_BH(buf));
        const uint32_t* sBl = (const uint32_t*)(smem + HG_BL(buf));

        #pragma unroll
        for (int ks = 0; ks < 4; ks++) {
            uint4 a1[4], a2[4];
            uint2 b1[4], b2[4];
            #pragma unroll
            for (int mt = 0; mt < 4; mt++) {
                const int o = (((wr * 4 + mt) * 4 + ks) * 32 + lane) * 4;
                a1[mt] = *reinterpret_cast<const uint4*>(sAh + o);
                a2[mt] = *reinterpret_cast<const uint4*>(sAl + o);
            }
            #pragma unroll
            for (int nt = 0; nt < 4; nt++) {
                const int o = (((wc * 4 + nt) * 4 + ks) * 32 + lane) * 2;
                b1[nt] = *reinterpret_cast<const uint2*>(sBh + o);
                b2[nt] = *reinterpret_cast<const uint2*>(sBl + o);
            }
            #pragma unroll
            for (int mt = 0; mt < 4; mt++)
                #pragma unroll
                for (int nt = 0; nt < 4; nt++)
                    mma_f16(acc[mt][nt], a1[mt].x, a1[mt].y, a1[mt].z, a1[mt].w,
                            b1[nt].x, b1[nt].y);
            #pragma unroll
            for (int mt = 0; mt < 4; mt++)
                #pragma unroll
                for (int nt = 0; nt < 4; nt++)
                    mma_f16(acc[mt][nt], a1[mt].x, a1[mt].y, a1[mt].z, a1[mt].w,
                            b2[nt].x, b2[nt].y);
            #pragma unroll
            for (int mt = 0; mt < 4; mt++)
                #pragma unroll
                for (int nt = 0; nt < 4; nt++)
                    mma_f16(acc[mt][nt], a2[mt].x, a2[mt].y, a2[mt].z, a2[mt].w,
                            b1[nt].x, b1[nt].y);
            #pragma unroll
            for (int mt = 0; mt < 4; mt++)
                #pragma unroll
                for (int nt = 0; nt < 4; nt++)
                    mma_f16(acc[mt][nt], a2[mt].x, a2[mt].y, a2[mt].z, a2[mt].w,
                            b2[nt].x, b2[nt].y);
        }
        __syncthreads();
    }

    // ---- bias (+ReLU) in place ----
    #pragma unroll
    for (int nt = 0; nt < 4; nt++) {
        const int c0 = blockIdx.x * 128 + wc * 32 + nt * 8 + 2 * (lane & 3);
        const float bv0 = bias[c0], bv1 = bias[c0 + 1];
        #pragma unroll
        for (int mt = 0; mt < 4; mt++) {
            acc[mt][nt][0] += bv0;
            acc[mt][nt][1] += bv1;
            acc[mt][nt][2] += bv0;
            acc[mt][nt][3] += bv1;
            if (EPI == 1) {
                acc[mt][nt][0] = fmaxf(acc[mt][nt][0], 0.f);
                acc[mt][nt][1] = fmaxf(acc[mt][nt][1], 0.f);
                acc[mt][nt][2] = fmaxf(acc[mt][nt][2], 0.f);
                acc[mt][nt][3] = fmaxf(acc[mt][nt][3], 0.f);
            }
        }
    }

    if (FRAGOUT) {
        // emit as fp16 hi/lo A-fragments of a [M, 256] matrix (k16 steps)
        #pragma unroll
        for (int mt = 0; mt < 4; mt++) {
            const int mtg_glob = blockIdx.y * 8 + wr * 4 + mt;
            #pragma unroll
            for (int ntp = 0; ntp < 2; ntp++) {
                const int ks_glob = blockIdx.x * 8 + wc * 2 + ntp;
                uint4 h, l;
                split2(acc[mt][2 * ntp][0],     acc[mt][2 * ntp][1],     h.x, l.x);
                split2(acc[mt][2 * ntp][2],     acc[mt][2 * ntp][3],     h.y, l.y);
                split2(acc[mt][2 * ntp + 1][0], acc[mt][2 * ntp + 1][1], h.z, l.z);
                split2(acc[mt][2 * ntp + 1][2], acc[mt][2 * ntp + 1][3], h.w, l.w);
                const size_t o = ((size_t)(mtg_glob * 16 + ks_glob) * 32 + lane) * 4;
                *reinterpret_cast<uint4*>(dh + o) = h;
                *reinterpret_cast<uint4*>(dl + o) = l;
            }
        }
    } else {
        #pragma unroll
        for (int nt = 0; nt < 4; nt++) {
            const int c0 = blockIdx.x * 128 + wc * 32 + nt * 8 + 2 * (lane & 3);
            #pragma unroll
            for (int mt = 0; mt < 4; mt++) {
                const int r = blockIdx.y * 128 + wr * 64 + mt * 16 + (lane >> 2);
                *reinterpret_cast<float2*>(C + (size_t)r * HH + c0) =
                    make_float2(acc[mt][nt][0], acc[mt][nt][1]);
                *reinterpret_cast<float2*>(C + (size_t)(r + 8) * HH + c0) =
                    make_float2(acc[mt][nt][2], acc[mt][nt][3]);
            }
        }
    }

    if (BNACC) {
        float* red = (float*)(smem + HG_RED);
        float cs[8], cq[8];
        #pragma unroll
        for (int j = 0; j < 8; j++) { cs[j] = 0.f; cq[j] = 0.f; }
        #pragma unroll
        for (int nt = 0; nt < 4; nt++)
            #pragma unroll
            for (int mt = 0; mt < 4; mt++) {
                const float v0 = acc[mt][nt][0], v1 = acc[mt][nt][1];
                const float v2 = acc[mt][nt][2], v3 = acc[mt][nt][3];
                cs[nt * 2 + 0] += v0 + v2;
                cs[nt * 2 + 1] += v1 + v3;
                cq[nt * 2 + 0] = fmaf(v0, v0, fmaf(v2, v2, cq[nt * 2 + 0]));
                cq[nt * 2 + 1] = fmaf(v1, v1, fmaf(v3, v3, cq[nt * 2 + 1]));
            }
        const int slot = wr * 8 + (lane >> 2);
        #pragma unroll
        for (int nt = 0; nt < 4; nt++) {
            #pragma unroll
            for (int h = 0; h < 2; h++) {
                const int cl = wc * 32 + nt * 8 + 2 * (lane & 3) + h;
                red[cl * 16 + slot]        = cs[nt * 2 + h];
                red[2048 + cl * 16 + slot] = cq[nt * 2 + h];
            }
        }
        __syncthreads();
        if (tid < 128) {
            float s = 0.f, q = 0.f;
            #pragma unroll
            for (int t = 0; t < 16; t++) {
                s += red[tid * 16 + t];
                q += red[2048 + tid * 16 + t];
            }
            ps[(size_t)blockIdx.y * HH + blockIdx.x * 128 + tid] = s;
            pq[(size_t)blockIdx.y * HH + blockIdx.x * 128 + tid] = q;
        }
    }
}

// ================= GEMM3: fp16 4-term, 128x64 CTA, tanh, fragment output ======
// warps: wr = wid>>2 (0..1, 64 rows each), wc = wid&3 (0..3, 16 cols each)
#define H3_AH(b) ((b) * 32768)
#define H3_AL(b) (H3_AH(b) + 16384)
#define H3_BH(b) (65536 + (b) * 16384)
#define H3_BL(b) (H3_BH(b) + 8192)
#define H3_SMEM  98304

__global__ void __launch_bounds__(256, 1) hgemm3_kernel(
    const uint32_t* __restrict__ Ah, const uint32_t* __restrict__ Al,
    const float* __restrict__ bias,
    uint32_t* __restrict__ dh, uint32_t* __restrict__ dl)
{
    extern __shared__ char smem[];
    const uint32_t sb = smem_u32(smem);

    const int tid  = threadIdx.x;
    const int lane = tid & 31;
    const int wid  = tid >> 5;
    const int wr   = wid >> 2;
    const int wc   = wid & 3;
    const int mtg0 = blockIdx.x * 8;

    auto prefetch = [&](int buf, int ck) {
        #pragma unroll
        for (int t = 0; t < 4; t++) {
            const int bi = t * 8 + (tid >> 5);
            const int mt = bi >> 2, ksl = bi & 3;
            const size_t gsrc = ((size_t)((mtg0 + mt) * 16 + ck * 4 + ksl)) * 128 + (tid & 31) * 4;
            const uint32_t doff = (uint32_t)(((mt * 4 + ksl) * 128 + (tid & 31) * 4) << 2);
            cp16(sb + H3_AH(buf) + doff, Ah + gsrc);
            cp16(sb + H3_AL(buf) + doff, Al + gsrc);
        }
        #pragma unroll
        for (int t = 0; t < 2; t++) {
            const int bi = t * 16 + (tid >> 4);
            const int nt = bi >> 2, ksl = bi & 3;
            const size_t gsrc = ((size_t)(nt * 16 + ck * 4 + ksl)) * 64 + (tid & 15) * 4;
            const uint32_t doff = (uint32_t)(((nt * 4 + ksl) * 64 + (tid & 15) * 4) << 2);
            cp16(sb + H3_BH(buf) + doff, g_w3h + gsrc);
            cp16(sb + H3_BL(buf) + doff, g_w3l + gsrc);
        }
        CP_COMMIT();
    };

    prefetch(0, 0);

    float acc[4][2][4];
    #pragma unroll
    for (int mt = 0; mt < 4; mt++)
        #pragma unroll
        for (int nt = 0; nt < 2; nt++)
            #pragma unroll
            for (int j = 0; j < 4; j++) acc[mt][nt][j] = 0.f;

    for (int ck = 0; ck < 4; ck++) {
        const int buf = ck & 1;
        CP_WAIT0();
        __syncthreads();
        if (ck + 1 < 4) prefetch(buf ^ 1, ck + 1);

        const uint32_t* sAh = (const uint32_t*)(smem + H3_AH(buf));
        const uint32_t* sAl = (const uint32_t*)(smem + H3_AL(buf));
        const uint32_t* sBh = (const uint32_t*)(smem + H3_BH(buf));
        const uint32_t* sBl = (const uint32_t*)(smem + H3_BL(buf));

        #pragma unroll
        for (int ks = 0; ks < 4; ks++) {
            uint4 a1[4], a2[4];
            uint2 b1[2], b2[2];
            #pragma unroll
            for (int mt = 0; mt < 4; mt++) {
                const int o = (((wr * 4 + mt) * 4 + ks) * 32 + lane) * 4;
                a1[mt] = *reinterpret_cast<const uint4*>(sAh + o);
                a2[mt] = *reinterpret_cast<const uint4*>(sAl + o);
            }
            #pragma unroll
            for (int nt = 0; nt < 2; nt++) {
                const int o = (((wc * 2 + nt) * 4 + ks) * 32 + lane) * 2;
                b1[nt] = *reinterpret_cast<const uint2*>(sBh + o);
                b2[nt] = *reinterpret_cast<const uint2*>(sBl + o);
            }
            #pragma unroll
            for (int mt = 0; mt < 4; mt++)
                #pragma unroll
                for (int nt = 0; nt < 2; nt++) {
                    mma_f16(acc[mt][nt], a1[mt].x, a1[mt].y, a1[mt].z, a1[mt].w,
                            b1[nt].x, b1[nt].y);
                    mma_f16(acc[mt][nt], a1[mt].x, a1[mt].y, a1[mt].z, a1[mt].w,
                            b2[nt].x, b2[nt].y);
                    mma_f16(acc[mt][nt], a2[mt].x, a2[mt].y, a2[mt].z, a2[mt].w,
                            b1[nt].x, b1[nt].y);
                    mma_f16(acc[mt][nt], a2[mt].x, a2[mt].y, a2[mt].z, a2[mt].w,
                            b2[nt].x, b2[nt].y);
                }
        }
        __syncthreads();
    }

    // ---- tanh epilogue + z A-fragment output (ks_z = wc) ----
    #pragma unroll
    for (int mt = 0; mt < 4; mt++) {
        const int mtg_glob = blockIdx.x * 8 + wr * 4 + mt;
        float v[2][4];
        #pragma unroll
        for (int nt = 0; nt < 2; nt++) {
            const int c0 = wc * 16 + nt * 8 + 2 * (lane & 3);
            const float bv0 = bias[c0], bv1 = bias[c0 + 1];
            v[nt][0] = tanhf(acc[mt][nt][0] + bv0);
            v[nt][1] = tanhf(acc[mt][nt][1] + bv1);
            v[nt][2] = tanhf(acc[mt][nt][2] + bv0);
            v[nt][3] = tanhf(acc[mt][nt][3] + bv1);
        }
        uint4 h, l;
        split2(v[0][0], v[0][1], h.x, l.x);
        split2(v[0][2], v[0][3], h.y, l.y);
        split2(v[1][0], v[1][1], h.z, l.z);
        split2(v[1][2], v[1][3], h.w, l.w);
        const size_t o = ((size_t)(mtg_glob * 4 + wc) * 32 + lane) * 4;
        *reinterpret_cast<uint4*>(dh + o) = h;
        *reinterpret_cast<uint4*>(dl + o) = l;
    }
}

// ---------------- BN finalize: parallel two-stage -----------------
__global__ void bn_stage1_kernel()
{
    const int j = threadIdx.x;
    const int b0 = blockIdx.x * 32;
    float s = 0.f, q = 0.f;
    #pragma unroll 8
    for (int r = 0; r < 32; r++) {
        s += g_ps[(size_t)(b0 + r) * HH + j];
        q += g_pq[(size_t)(b0 + r) * HH + j];
    }
    g_ps2[blockIdx.x * HH + j] = s;
    g_pq2[blockIdx.x * HH + j] = q;
}

__global__ void bn_stage2_kernel(const float* __restrict__ gamma,
                                 const float* __restrict__ beta)
{
    const int j = threadIdx.x;
    float s = 0.f, q = 0.f;
    #pragma unroll
    for (int b = 0; b < 16; b++) { s += g_ps2[b * HH + j]; q += g_pq2[b * HH + j]; }
    const float mean = s * (1.f / (float)BB);
    const float var  = q * (1.f / (float)BB) - mean * mean;
    const float inv  = rsqrtf(var + 1e-5f);
    const float sc   = gamma[j] * inv;
    g_scale[j] = sc;
    g_shift[j] = beta[j] - mean * sc;
}

// ---------------- codebook squared norms: warp per code, coalesced -----------
__global__ void __launch_bounds__(256) c2_kernel(const float* __restrict__ cb)
{
    const int code = (blockIdx.x * 256 + threadIdx.x) >> 5;
    const int lane = threadIdx.x & 31;
    const float2 v = *reinterpret_cast<const float2*>(cb + (size_t)code * DE + lane * 2);
    float s = fmaf(v.x, v.x, v.y * v.y);
    #pragma unroll
    for (int off = 16; off > 0; off >>= 1)
        s += __shfl_down_sync(0xffffffff, s, off);
    if (lane == 0) g_c2[code] = s;
}

// ---------------- codebook -> fp16 hi/lo B-fragments (dist, per chunk) ---------
__global__ void cvt_cb_kernel(const float* __restrict__ cb)
{
    const int ch = blockIdx.x;
    const int tid = threadIdx.x;
    const float* src = cb + (size_t)ch * 8192;
    #pragma unroll
    for (int t = 0; t < 16; t++) {
        const int lin = t * 256 + tid;
        const int n = lin >> 5, k2 = lin & 31;
        const float2 v = *reinterpret_cast<const float2*>(src + n * 64 + 2 * k2);
        uint32_t h, l;
        split2(v.x, v.y, h, l);
        const int nt = n >> 3, nn = n & 7;
        const int ks = k2 >> 3, kk2 = k2 & 7;
        const int o = ((nt * 4 + ks) * 32 + nn * 4 + (kk2 & 3)) * 2 + (kk2 >> 2);
        g_cb1[ch * 4096 + o] = h;
        g_cb2[ch * 4096 + o] = l;
    }
}

// ================= fp16 3-term split dist + argmin (z fragments prebuilt) ======
#define D_A1   0
#define D_A2   16384
#define D_B1(buf) (32768 + (buf) * 32768)
#define D_B2(buf) (D_B1(buf) + 16384)
#define D_C2   98304
#define D_REDF 99328
#define D_REDI 107520
#define D_SMEM 115712

__global__ void __launch_bounds__(256, 1) dist_argmin_mma(int* __restrict__ idxo)
{
    extern __shared__ char smem[];
    const uint32_t sb = smem_u32(smem);
    float* c2s  = (float*)(smem + D_C2);
    float* redF = (float*)(smem + D_REDF);
    int*   redI = (int*)(smem + D_REDI);

    const int tid  = threadIdx.x;
    const int lane = tid & 31;
    const int wid  = tid >> 5;
    const int wr   = wid >> 2;
    const int wc   = wid & 3;
    const int row0 = blockIdx.x * 128;

    // ---- async prefetch: z A-fragments (this tile) + chunk-0 B fragments ----
    {
        const uint4* zh = (const uint4*)(g_zfh + (size_t)blockIdx.x * 4096);
        const uint4* zl = (const uint4*)(g_zfl + (size_t)blockIdx.x * 4096);
        #pragma unroll
        for (int t = 0; t < 4; t++) {
            cp16(sb + D_A1 + (t * 256 + tid) * 16, zh + t * 256 + tid);
            cp16(sb + D_A2 + (t * 256 + tid) * 16, zl + t * 256 + tid);
        }
        const uint4* g1 = (const uint4*)(g_cb1);
        const uint4* g2 = (const uint4*)(g_cb2);
        #pragma unroll
        for (int t = 0; t < 4; t++) {
            cp16(sb + D_B1(0) + (t * 256 + tid) * 16, g1 + t * 256 + tid);
            cp16(sb + D_B2(0) + (t * 256 + tid) * 16, g2 + t * 256 + tid);
        }
        if (tid < 32) cp16(sb + D_C2 + tid * 16, (const uint4*)g_c2 + tid);
        CP_COMMIT();
    }

    const uint32_t* sA1 = (const uint32_t*)(smem + D_A1);
    const uint32_t* sA2 = (const uint32_t*)(smem + D_A2);

    float bestv[8];
    int   besti[8];
    #pragma unroll
    for (int s = 0; s < 8; s++) { bestv[s] = 3.4e38f; besti[s] = 0; }

    for (int ch = 0; ch < 32; ch++) {
        const int buf = ch & 1;
        CP_WAIT0();
        __syncthreads();

        if (ch + 1 < 32) {
            const uint4* g1 = (const uint4*)(g_cb1 + (ch + 1) * 4096);
            const uint4* g2 = (const uint4*)(g_cb2 + (ch + 1) * 4096);
            const uint32_t b1 = sb + D_B1(buf ^ 1);
            const uint32_t b2 = sb + D_B2(buf ^ 1);
            #pragma unroll
            for (int t = 0; t < 4; t++) {
                cp16(b1 + (t * 256 + tid) * 16, g1 + t * 256 + tid);
                cp16(b2 + (t * 256 + tid) * 16, g2 + t * 256 + tid);
            }
            if (tid < 32)
                cp16(sb + D_C2 + (buf ^ 1) * 512 + tid * 16,
                     (const uint4*)(g_c2 + (ch + 1) * 128) + tid);
            CP_COMMIT();
        }

        const uint32_t* sB1 = (const uint32_t*)(smem + D_B1(buf));
        const uint32_t* sB2 = (const uint32_t*)(smem + D_B2(buf));

        float acc[4][4][4];
        #pragma unroll
        for (int mt = 0; mt < 4; mt++)
            #pragma unroll
            for (int nt = 0; nt < 4; nt++)
                #pragma unroll
                for (int j = 0; j < 4; j++) acc[mt][nt][j] = 0.f;

        #pragma unroll
        for (int ks = 0; ks < 4; ks++) {
            uint4 a1[4], a2[4];
            uint2 b1[4], b2[4];
            #pragma unroll
            for (int mt = 0; mt < 4; mt++) {
                const int o = (((wr * 4 + mt) * 4 + ks) * 32 + lane) * 4;
                a1[mt] = *reinterpret_cast<const uint4*>(sA1 + o);
                a2[mt] = *reinterpret_cast<const uint4*>(sA2 + o);
            }
            #pragma unroll
            for (int nt = 0; nt < 4; nt++) {
                const int o = (((wc * 4 + nt) * 4 + ks) * 32 + lane) * 2;
                b1[nt] = *reinterpret_cast<const uint2*>(sB1 + o);
                b2[nt] = *reinterpret_cast<const uint2*>(sB2 + o);
            }
            #pragma unroll
            for (int mt = 0; mt < 4; mt++)
                #pragma unroll
                for (int nt = 0; nt < 4; nt++)
                    mma_f16(acc[mt][nt], a1[mt].x, a1[mt].y, a1[mt].z, a1[mt].w,
                            b1[nt].x, b1[nt].y);
            #pragma unroll
            for (int mt = 0; mt < 4; mt++)
                #pragma unroll
                for (int nt = 0; nt < 4; nt++)
                    mma_f16(acc[mt][nt], a1[mt].x, a1[mt].y, a1[mt].z, a1[mt].w,
                            b2[nt].x, b2[nt].y);
            #pragma unroll
            for (int mt = 0; mt < 4; mt++)
                #pragma unroll
                for (int nt = 0; nt < 4; nt++)
                    mma_f16(acc[mt][nt], a2[mt].x, a2[mt].y, a2[mt].z, a2[mt].w,
                            b1[nt].x, b1[nt].y);
        }

        const float* c2p = c2s + buf * 128;
        #pragma unroll
        for (int nt = 0; nt < 4; nt++) {
            const int ncol = wc * 32 + nt * 8 + 2 * (lane & 3);
            const float cc0 = c2p[ncol];
            const float cc1 = c2p[ncol + 1];
            const int gi = ch * 128 + ncol;
            #pragma unroll
            for (int mt = 0; mt < 4; mt++) {
                const float d0 = fmaf(-2.f, acc[mt][nt][0], cc0);
                const float d1 = fmaf(-2.f, acc[mt][nt][1], cc1);
                const float d2 = fmaf(-2.f, acc[mt][nt][2], cc0);
                const float d3 = fmaf(-2.f, acc[mt][nt][3], cc1);
                const int s0 = mt * 2, s1 = mt * 2 + 1;
                if (d0 < bestv[s0]) { bestv[s0] = d0; besti[s0] = gi; }
                if (d1 < bestv[s0]) { bestv[s0] = d1; besti[s0] = gi + 1; }
                if (d2 < bestv[s1]) { bestv[s1] = d2; besti[s1] = gi; }
                if (d3 < bestv[s1]) { bestv[s1] = d3; besti[s1] = gi + 1; }
            }
        }
        __syncthreads();
    }

    #pragma unroll
    for (int s = 0; s < 8; s++) {
        const int mt = s >> 1, half = s & 1;
        const int row = wr * 64 + mt * 16 + half * 8 + (lane >> 2);
        const int e = wc * 4 + (lane & 3);
        redF[row * 16 + e] = bestv[s];
        redI[row * 16 + e] = besti[s];
    }
    __syncthreads();
    if (tid < 128) {
        float bs = 3.4e38f;
        int   b  = 0x7fffffff;
        #pragma unroll
        for (int e = 0; e < 16; e++) {
            const float sv = redF[tid * 16 + e];
            const int   iv = redI[tid * 16 + e];
            if (sv < bs || (sv == bs && iv < b)) { bs = sv; b = iv; }
        }
        idxo[row0 + tid] = b;
    }
}

// ---------------- output writer ----------------
__global__ void writeout_kernel(const float* __restrict__ cb,
                                float* __restrict__ outf, int* __restrict__ outi,
                                int mode)
{
    const int gid = blockIdx.x * 256 + threadIdx.x;
    const int row = gid >> 6, j = gid & 63;
    const int id = g_idx[row];
    if (mode == 0) {
        if (j == 0) outf[row] = (float)id;
        outf[BB + gid] = cb[(size_t)id * DE + j];
    } else if (mode == 1) {
        outf[gid] = cb[(size_t)id * DE + j];
    } else {
        if (j == 0) outi[row] = id;
    }
}

// ---------------- launch -----------------------------------------------------------
extern "C" void kernel_launch(void* const* d_in, const int* in_sizes, int n_in,
                              void* d_out, int out_size)
{
    const float* x     = (const float*)d_in[0];
    const float* W1    = (const float*)d_in[1];
    const float* b1    = (const float*)d_in[2];
    const float* gamma = (const float*)d_in[3];
    const float* beta  = (const float*)d_in[4];
    const float* W2    = (const float*)d_in[5];
    const float* b2    = (const float*)d_in[6];
    const float* W3    = (const float*)d_in[7];
    const float* b3    = (const float*)d_in[8];
    const float* cb    = (const float*)d_in[9];

    float *h1p = nullptr, *psp = nullptr, *pqp = nullptr;
    int *idxp = nullptr;
    uint32_t *a1h, *a1l, *a2h, *a2l, *a3h, *a3l, *zfh, *zfl;
    uint32_t *w1h, *w1l, *w2h, *w2l, *w3h, *w3l;
    cudaGetSymbolAddress((void**)&h1p, g_h1);
    cudaGetSymbolAddress((void**)&psp, g_ps);
    cudaGetSymbolAddress((void**)&pqp, g_pq);
    cudaGetSymbolAddress((void**)&idxp, g_idx);
    cudaGetSymbolAddress((void**)&a1h, g_af1h);
    cudaGetSymbolAddress((void**)&a1l, g_af1l);
    cudaGetSymbolAddress((void**)&a2h, g_af2h);
    cudaGetSymbolAddress((void**)&a2l, g_af2l);
    cudaGetSymbolAddress((void**)&a3h, g_af3h);
    cudaGetSymbolAddress((void**)&a3l, g_af3l);
    cudaGetSymbolAddress((void**)&zfh, g_zfh);
    cudaGetSymbolAddress((void**)&zfl, g_zfl);
    cudaGetSymbolAddress((void**)&w1h, g_w1h);
    cudaGetSymbolAddress((void**)&w1l, g_w1l);
    cudaGetSymbolAddress((void**)&w2h, g_w2h);
    cudaGetSymbolAddress((void**)&w2l, g_w2l);
    cudaGetSymbolAddress((void**)&w3h, g_w3h);
    cudaGetSymbolAddress((void**)&w3l, g_w3l);

    cudaFuncSetAttribute(dist_argmin_mma, cudaFuncAttributeMaxDynamicSharedMemorySize, D_SMEM);
    cudaFuncSetAttribute(hgemm_kernel<8, 0, true, false>,
                         cudaFuncAttributeMaxDynamicSharedMemorySize, HG_SMEM(true));
    cudaFuncSetAttribute(hgemm_kernel<16, 1, false, true>,
                         cudaFuncAttributeMaxDynamicSharedMemorySize, HG_SMEM(false));
    cudaFuncSetAttribute(hgemm3_kernel, cudaFuncAttributeMaxDynamicSharedMemorySize, H3_SMEM);

    dim3 blk(256);

    // prep: operand conversions + codebook norms
    cvt_a_kernel<8, false><<<4096, blk>>>(x, a1h, a1l);
    cvt_w_kernel<<<32, blk>>>(W1, w1h, w1l, 8, 256);
    cvt_w_kernel<<<64, blk>>>(W2, w2h, w2l, 16, 256);
    cvt_w_kernel<<<16, blk>>>(W3, w3h, w3l, 16, 64);
    c2_kernel<<<512, blk>>>(cb);
    cvt_cb_kernel<<<32, blk>>>(cb);

    // h1 = x @ W1 + b1 (fp16 4-term), fp32 out + fused BN partial sums
    hgemm_kernel<8, 0, true, false><<<dim3(2, BB / 128), blk, HG_SMEM(true)>>>(
        a1h, a1l, w1h, w1l, b1, h1p, psp, pqp, nullptr, nullptr);

    // BN finalize
    bn_stage1_kernel<<<16, HH>>>();
    bn_stage2_kernel<<<1, HH>>>(gamma, beta);

    // bnrelu(h1) -> A fragments
    cvt_a_kernel<16, true><<<8192, blk>>>(h1p, a2h, a2l);

    // h2 = relu( bnrelu(h1) @ W2 + b2 ) (fp16 4-term), output AS fp16 A-fragments
    hgemm_kernel<16, 1, false, true><<<dim3(2, BB / 128), blk, HG_SMEM(false)>>>(
        a2h, a2l, w2h, w2l, b2, nullptr, nullptr, nullptr, a3h, a3l);

    // z = tanh( h2 @ W3 + b3 ) (fp16 4-term), output AS z A-fragments
    hgemm3_kernel<<<BB / 128, blk, H3_SMEM>>>(a3h, a3l, b3, zfh, zfl);

    // dist/argmin (fp16 3-term split, prebuilt z fragments)
    dist_argmin_mma<<<BB / 128, blk, D_SMEM>>>(idxp);

    // outputs
    int mode;
    if      (out_size == BB * (DE + 1)) mode = 0;
    else if (out_size == BB * DE)       mode = 1;
    else                                mode = 2;
    writeout_kernel<<<(BB * DE) / 256, blk>>>(cb, (float*)d_out, (int*)d_out, mode);
}

// round 10
// speedup vs baseline: 3.3252x; 1.1729x over previous
#include <cuda_runtime.h>
#include <cuda_fp16.h>
#include <math.h>
#include <stdint.h>

#define BB  65536
#define DIN 128
#define HH  256
#define DE  64
#define KC  4096

// ---------------- scratch (static device globals; no allocation) ----------------
__device__ float g_h1[(size_t)BB * HH];
__device__ float g_ps[512 * HH];
__device__ float g_pq[512 * HH];
__device__ float g_ps2[16 * HH];
__device__ float g_pq2[16 * HH];
__device__ float g_scale[HH];
__device__ float g_shift[HH];
__device__ float g_c2[KC];
__device__ float g_bv[2 * BB];               // per-half best value
__device__ int   g_bi[2 * BB];               // per-half best index
__device__ uint32_t g_cb1[32 * 4096];        // codebook fp16-hi B-fragments (dist)
__device__ uint32_t g_cb2[32 * 4096];        // codebook fp16-lo
__device__ uint32_t g_af1h[4096 * 8 * 128];  // x A-fragments hi (K=128)
__device__ uint32_t g_af1l[4096 * 8 * 128];
__device__ uint32_t g_af2h[4096 * 16 * 128]; // bnrelu(h1) A-fragments (K=256)
__device__ uint32_t g_af2l[4096 * 16 * 128];
__device__ uint32_t g_af3h[4096 * 16 * 128]; // h2 A-fragments (K=256)
__device__ uint32_t g_af3l[4096 * 16 * 128];
__device__ uint32_t g_zfh[4096 * 4 * 128];   // z A-fragments (K=64)
__device__ uint32_t g_zfl[4096 * 4 * 128];
__device__ uint32_t g_w1h[32 * 8 * 64];
__device__ uint32_t g_w1l[32 * 8 * 64];
__device__ uint32_t g_w2h[32 * 16 * 64];
__device__ uint32_t g_w2l[32 * 16 * 64];
__device__ uint32_t g_w3h[8 * 16 * 64];
__device__ uint32_t g_w3l[8 * 16 * 64];

__device__ __forceinline__ uint32_t smem_u32(const void* p) {
    uint32_t a;
    asm("{ .reg .u64 t; cvta.to.shared.u64 t, %1; cvt.u32.u64 %0, t; }" : "=r"(a) : "l"(p));
    return a;
}
__device__ __forceinline__ void cp16(uint32_t dst, const void* src) {
    asm volatile("cp.async.cg.shared.global [%0], [%1], 16;" :: "r"(dst), "l"(src));
}
#define CP_COMMIT() asm volatile("cp.async.commit_group;" ::: "memory")
#define CP_WAIT0()  asm volatile("cp.async.wait_group 0;" ::: "memory")

__device__ __forceinline__ uint32_t packh2(float a, float b) {
    __half2 t = __floats2half2_rn(a, b);
    return *reinterpret_cast<uint32_t*>(&t);
}
__device__ __forceinline__ void split2(float a, float b, uint32_t& h, uint32_t& l) {
    h = packh2(a, b);
    const float ra = a - __half2float(__float2half_rn(a));
    const float rb = b - __half2float(__float2half_rn(b));
    l = packh2(ra, rb);
}
__device__ __forceinline__ void mma_f16(float c[4], uint32_t a0, uint32_t a1,
                                        uint32_t a2, uint32_t a3,
                                        uint32_t b0, uint32_t b1) {
    asm volatile(
        "mma.sync.aligned.m16n8k16.row.col.f32.f16.f16.f32 "
        "{%0,%1,%2,%3}, {%4,%5,%6,%7}, {%8,%9}, {%0,%1,%2,%3};"
        : "+f"(c[0]), "+f"(c[1]), "+f"(c[2]), "+f"(c[3])
        : "r"(a0), "r"(a1), "r"(a2), "r"(a3), "r"(b0), "r"(b1));
}

// ================= A-operand -> fp16 hi/lo fragments (m16n8k16 row A) =========
template<int KST, bool BN>
__global__ void __launch_bounds__(256) cvt_a_kernel(
    const float* __restrict__ A, uint32_t* __restrict__ dh, uint32_t* __restrict__ dl)
{
    constexpr int K = KST * 16;
    constexpr int LK = (KST == 8) ? 3 : 4;
    const int gid = blockIdx.x * 256 + threadIdx.x;
    const int lane = gid & 31;
    const int ks = (gid >> 5) & (KST - 1);
    const int mtg = gid >> (5 + LK);

    const int r0 = mtg * 16 + (lane >> 2);
    const int kb = ks * 16 + 2 * (lane & 3);

    float2 v00 = *reinterpret_cast<const float2*>(A + (size_t)r0 * K + kb);
    float2 v02 = *reinterpret_cast<const float2*>(A + (size_t)r0 * K + kb + 8);
    float2 v10 = *reinterpret_cast<const float2*>(A + (size_t)(r0 + 8) * K + kb);
    float2 v12 = *reinterpret_cast<const float2*>(A + (size_t)(r0 + 8) * K + kb + 8);

    if (BN) {
        const float s0 = g_scale[kb],     t0 = g_shift[kb];
        const float s1 = g_scale[kb + 1], t1 = g_shift[kb + 1];
        const float s2 = g_scale[kb + 8], t2 = g_shift[kb + 8];
        const float s3 = g_scale[kb + 9], t3 = g_shift[kb + 9];
        v00.x = fmaxf(fmaf(v00.x, s0, t0), 0.f); v00.y = fmaxf(fmaf(v00.y, s1, t1), 0.f);
        v02.x = fmaxf(fmaf(v02.x, s2, t2), 0.f); v02.y = fmaxf(fmaf(v02.y, s3, t3), 0.f);
        v10.x = fmaxf(fmaf(v10.x, s0, t0), 0.f); v10.y = fmaxf(fmaf(v10.y, s1, t1), 0.f);
        v12.x = fmaxf(fmaf(v12.x, s2, t2), 0.f); v12.y = fmaxf(fmaf(v12.y, s3, t3), 0.f);
    }

    uint4 h, l;
    split2(v00.x, v00.y, h.x, l.x);
    split2(v10.x, v10.y, h.y, l.y);
    split2(v02.x, v02.y, h.z, l.z);
    split2(v12.x, v12.y, h.w, l.w);

    const size_t o = ((size_t)(mtg * KST + ks) * 32 + lane) * 4;
    *reinterpret_cast<uint4*>(dh + o) = h;
    *reinterpret_cast<uint4*>(dl + o) = l;
}

// ================= W -> fp16 hi/lo B-fragments (col B) ========================
__global__ void __launch_bounds__(256) cvt_w_kernel(
    const float* __restrict__ W, uint32_t* __restrict__ dh, uint32_t* __restrict__ dl,
    int KST, int N)
{
    const int gid = blockIdx.x * 256 + threadIdx.x;
    const int lane = gid & 31;
    const int ks = (gid >> 5) % KST;
    const int ntg = gid / (32 * KST);

    const int n = ntg * 8 + (lane >> 2);
    const int k0 = ks * 16 + 2 * (lane & 3);

    uint2 h, l;
    split2(W[(size_t)k0 * N + n],       W[(size_t)(k0 + 1) * N + n], h.x, l.x);
    split2(W[(size_t)(k0 + 8) * N + n], W[(size_t)(k0 + 9) * N + n], h.y, l.y);

    const size_t o = ((size_t)(ntg * KST + ks) * 32 + lane) * 2;
    *reinterpret_cast<uint2*>(dh + o) = h;
    *reinterpret_cast<uint2*>(dl + o) = l;
}

// ================= fp16 3-term split tensor GEMM, 128x128 CTA tile ============
#define HG_AH(b) ((b) * 32768)
#define HG_AL(b) (HG_AH(b) + 16384)
#define HG_BH(b) (65536 + (b) * 32768)
#define HG_BL(b) (HG_BH(b) + 16384)
#define HG_RED   131072
#define HG_SMEM(bnacc) (131072 + ((bnacc) ? 16384 : 0))

template<int KST>
__device__ __forceinline__ void hg_prefetch(
    uint32_t sb, int buf, int ck,
    const uint32_t* __restrict__ Ah, const uint32_t* __restrict__ Al,
    const uint32_t* __restrict__ Bh, const uint32_t* __restrict__ Bl,
    int mtg0, int ntg0, int tid)
{
    #pragma unroll
    for (int t = 0; t < 4; t++) {
        const int bi = t * 8 + (tid >> 5);
        const int mt = bi >> 2, ksl = bi & 3;
        const size_t gsrc = ((size_t)((mtg0 + mt) * KST + ck * 4 + ksl)) * 128 + (tid & 31) * 4;
        const uint32_t doff = (uint32_t)(((mt * 4 + ksl) * 128 + (tid & 31) * 4) << 2);
        cp16(sb + HG_AH(buf) + doff, Ah + gsrc);
        cp16(sb + HG_AL(buf) + doff, Al + gsrc);
    }
    #pragma unroll
    for (int t = 0; t < 4; t++) {
        const int bi = t * 16 + (tid >> 4);
        const int nt = bi >> 2, ksl = bi & 3;
        const size_t gsrc = ((size_t)((ntg0 + nt) * KST + ck * 4 + ksl)) * 64 + (tid & 15) * 4;
        const uint32_t doff = (uint32_t)(((nt * 4 + ksl) * 64 + (tid & 15) * 4) << 2);
        cp16(sb + HG_BH(buf) + doff, Bh + gsrc);
        cp16(sb + HG_BL(buf) + doff, Bl + gsrc);
    }
    CP_COMMIT();
}

template<int KST, int EPI, bool BNACC, bool FRAGOUT>
__global__ void __launch_bounds__(256, 1) hgemm_kernel(
    const uint32_t* __restrict__ Ah, const uint32_t* __restrict__ Al,
    const uint32_t* __restrict__ Bh, const uint32_t* __restrict__ Bl,
    const float* __restrict__ bias, float* __restrict__ C,
    float* __restrict__ ps, float* __restrict__ pq,
    uint32_t* __restrict__ dh, uint32_t* __restrict__ dl)
{
    extern __shared__ char smem[];
    const uint32_t sb = smem_u32(smem);
    constexpr int NCH = KST / 4;

    const int tid  = threadIdx.x;
    const int lane = tid & 31;
    const int wid  = tid >> 5;
    const int wr   = wid >> 2;
    const int wc   = wid & 3;
    const int mtg0 = blockIdx.y * 8;
    const int ntg0 = blockIdx.x * 16;

    hg_prefetch<KST>(sb, 0, 0, Ah, Al, Bh, Bl, mtg0, ntg0, tid);

    float acc[4][4][4];
    #pragma unroll
    for (int mt = 0; mt < 4; mt++)
        #pragma unroll
        for (int nt = 0; nt < 4; nt++)
            #pragma unroll
            for (int j = 0; j < 4; j++) acc[mt][nt][j] = 0.f;

    for (int ck = 0; ck < NCH; ck++) {
        const int buf = ck & 1;
        CP_WAIT0();
        __syncthreads();
        if (ck + 1 < NCH)
            hg_prefetch<KST>(sb, buf ^ 1, ck + 1, Ah, Al, Bh, Bl, mtg0, ntg0, tid);

        const uint32_t* sAh = (const uint32_t*)(smem + HG_AH(buf));
        const uint32_t* sAl = (const uint32_t*)(smem + HG_AL(buf));
        const uint32_t* sBh = (const uint32_t*)(smem + HG_BH(buf));
        const uint32_t* sBl = (const uint32_t*)(smem + HG_BL(buf));

        #pragma unroll
        for (int ks = 0; ks < 4; ks++) {
            uint4 a1[4], a2[4];
            uint2 b1[4], b2[4];
            #pragma unroll
            for (int mt = 0; mt < 4; mt++) {
                const int o = (((wr * 4 + mt) * 4 + ks) * 32 + lane) * 4;
                a1[mt] = *reinterpret_cast<const uint4*>(sAh + o);
                a2[mt] = *reinterpret_cast<const uint4*>(sAl + o);
            }
            #pragma unroll
            for (int nt = 0; nt < 4; nt++) {
                const int o = (((wc * 4 + nt) * 4 + ks) * 32 + lane) * 2;
                b1[nt] = *reinterpret_cast<const uint2*>(sBh + o);
                b2[nt] = *reinterpret_cast<const uint2*>(sBl + o);
            }
            #pragma unroll
            for (int mt = 0; mt < 4; mt++)
                #pragma unroll
                for (int nt = 0; nt < 4; nt++)
                    mma_f16(acc[mt][nt], a1[mt].x, a1[mt].y, a1[mt].z, a1[mt].w,
                            b1[nt].x, b1[nt].y);
            #pragma unroll
            for (int mt = 0; mt < 4; mt++)
                #pragma unroll
                for (int nt = 0; nt < 4; nt++)
                    mma_f16(acc[mt][nt], a1[mt].x, a1[mt].y, a1[mt].z, a1[mt].w,
                            b2[nt].x, b2[nt].y);
            #pragma unroll
            for (int mt = 0; mt < 4; mt++)
                #pragma unroll
                for (int nt = 0; nt < 4; nt++)
                    mma_f16(acc[mt][nt], a2[mt].x, a2[mt].y, a2[mt].z, a2[mt].w,
                            b1[nt].x, b1[nt].y);
        }
        __syncthreads();
    }

    // ---- bias (+ReLU) in place ----
    #pragma unroll
    for (int nt = 0; nt < 4; nt++) {
        const int c0 = blockIdx.x * 128 + wc * 32 + nt * 8 + 2 * (lane & 3);
        const float bv0 = bias[c0], bv1 = bias[c0 + 1];
        #pragma unroll
        for (int mt = 0; mt < 4; mt++) {
            acc[mt][nt][0] += bv0;
            acc[mt][nt][1] += bv1;
            acc[mt][nt][2] += bv0;
            acc[mt][nt][3] += bv1;
            if (EPI == 1) {
                acc[mt][nt][0] = fmaxf(acc[mt][nt][0], 0.f);
                acc[mt][nt][1] = fmaxf(acc[mt][nt][1], 0.f);
                acc[mt][nt][2] = fmaxf(acc[mt][nt][2], 0.f);
                acc[mt][nt][3] = fmaxf(acc[mt][nt][3], 0.f);
            }
        }
    }

    if (FRAGOUT) {
        #pragma unroll
        for (int mt = 0; mt < 4; mt++) {
            const int mtg_glob = blockIdx.y * 8 + wr * 4 + mt;
            #pragma unroll
            for (int ntp = 0; ntp < 2; ntp++) {
                const int ks_glob = blockIdx.x * 8 + wc * 2 + ntp;
                uint4 h, l;
                split2(acc[mt][2 * ntp][0],     acc[mt][2 * ntp][1],     h.x, l.x);
                split2(acc[mt][2 * ntp][2],     acc[mt][2 * ntp][3],     h.y, l.y);
                split2(acc[mt][2 * ntp + 1][0], acc[mt][2 * ntp + 1][1], h.z, l.z);
                split2(acc[mt][2 * ntp + 1][2], acc[mt][2 * ntp + 1][3], h.w, l.w);
                const size_t o = ((size_t)(mtg_glob * 16 + ks_glob) * 32 + lane) * 4;
                *reinterpret_cast<uint4*>(dh + o) = h;
                *reinterpret_cast<uint4*>(dl + o) = l;
            }
        }
    } else {
        #pragma unroll
        for (int nt = 0; nt < 4; nt++) {
            const int c0 = blockIdx.x * 128 + wc * 32 + nt * 8 + 2 * (lane & 3);
            #pragma unroll
            for (int mt = 0; mt < 4; mt++) {
                const int r = blockIdx.y * 128 + wr * 64 + mt * 16 + (lane >> 2);
                *reinterpret_cast<float2*>(C + (size_t)r * HH + c0) =
                    make_float2(acc[mt][nt][0], acc[mt][nt][1]);
                *reinterpret_cast<float2*>(C + (size_t)(r + 8) * HH + c0) =
                    make_float2(acc[mt][nt][2], acc[mt][nt][3]);
            }
        }
    }

    if (BNACC) {
        float* red = (float*)(smem + HG_RED);
        float cs[8], cq[8];
        #pragma unroll
        for (int j = 0; j < 8; j++) { cs[j] = 0.f; cq[j] = 0.f; }
        #pragma unroll
        for (int nt = 0; nt < 4; nt++)
            #pragma unroll
            for (int mt = 0; mt < 4; mt++) {
                const float v0 = acc[mt][nt][0], v1 = acc[mt][nt][1];
                const float v2 = acc[mt][nt][2], v3 = acc[mt][nt][3];
                cs[nt * 2 + 0] += v0 + v2;
                cs[nt * 2 + 1] += v1 + v3;
                cq[nt * 2 + 0] = fmaf(v0, v0, fmaf(v2, v2, cq[nt * 2 + 0]));
                cq[nt * 2 + 1] = fmaf(v1, v1, fmaf(v3, v3, cq[nt * 2 + 1]));
            }
        const int slot = wr * 8 + (lane >> 2);
        #pragma unroll
        for (int nt = 0; nt < 4; nt++) {
            #pragma unroll
            for (int h = 0; h < 2; h++) {
                const int cl = wc * 32 + nt * 8 + 2 * (lane & 3) + h;
                red[cl * 16 + slot]        = cs[nt * 2 + h];
                red[2048 + cl * 16 + slot] = cq[nt * 2 + h];
            }
        }
        __syncthreads();
        if (tid < 128) {
            float s = 0.f, q = 0.f;
            #pragma unroll
            for (int t = 0; t < 16; t++) {
                s += red[tid * 16 + t];
                q += red[2048 + tid * 16 + t];
            }
            ps[(size_t)blockIdx.y * HH + blockIdx.x * 128 + tid] = s;
            pq[(size_t)blockIdx.y * HH + blockIdx.x * 128 + tid] = q;
        }
    }
}

// ================= GEMM3: fp16 3-term, 128x64 CTA, tanh, fragment output ======
#define H3_AH(b) ((b) * 32768)
#define H3_AL(b) (H3_AH(b) + 16384)
#define H3_BH(b) (65536 + (b) * 16384)
#define H3_BL(b) (H3_BH(b) + 8192)
#define H3_SMEM  98304

__global__ void __launch_bounds__(256, 1) hgemm3_kernel(
    const uint32_t* __restrict__ Ah, const uint32_t* __restrict__ Al,
    const float* __restrict__ bias,
    uint32_t* __restrict__ dh, uint32_t* __restrict__ dl)
{
    extern __shared__ char smem[];
    const uint32_t sb = smem_u32(smem);

    const int tid  = threadIdx.x;
    const int lane = tid & 31;
    const int wid  = tid >> 5;
    const int wr   = wid >> 2;
    const int wc   = wid & 3;
    const int mtg0 = blockIdx.x * 8;

    auto prefetch = [&](int buf, int ck) {
        #pragma unroll
        for (int t = 0; t < 4; t++) {
            const int bi = t * 8 + (tid >> 5);
            const int mt = bi >> 2, ksl = bi & 3;
            const size_t gsrc = ((size_t)((mtg0 + mt) * 16 + ck * 4 + ksl)) * 128 + (tid & 31) * 4;
            const uint32_t doff = (uint32_t)(((mt * 4 + ksl) * 128 + (tid & 31) * 4) << 2);
            cp16(sb + H3_AH(buf) + doff, Ah + gsrc);
            cp16(sb + H3_AL(buf) + doff, Al + gsrc);
        }
        #pragma unroll
        for (int t = 0; t < 2; t++) {
            const int bi = t * 16 + (tid >> 4);
            const int nt = bi >> 2, ksl = bi & 3;
            const size_t gsrc = ((size_t)(nt * 16 + ck * 4 + ksl)) * 64 + (tid & 15) * 4;
            const uint32_t doff = (uint32_t)(((nt * 4 + ksl) * 64 + (tid & 15) * 4) << 2);
            cp16(sb + H3_BH(buf) + doff, g_w3h + gsrc);
            cp16(sb + H3_BL(buf) + doff, g_w3l + gsrc);
        }
        CP_COMMIT();
    };

    prefetch(0, 0);

    float acc[4][2][4];
    #pragma unroll
    for (int mt = 0; mt < 4; mt++)
        #pragma unroll
        for (int nt = 0; nt < 2; nt++)
            #pragma unroll
            for (int j = 0; j < 4; j++) acc[mt][nt][j] = 0.f;

    for (int ck = 0; ck < 4; ck++) {
        const int buf = ck & 1;
        CP_WAIT0();
        __syncthreads();
        if (ck + 1 < 4) prefetch(buf ^ 1, ck + 1);

        const uint32_t* sAh = (const uint32_t*)(smem + H3_AH(buf));
        const uint32_t* sAl = (const uint32_t*)(smem + H3_AL(buf));
        const uint32_t* sBh = (const uint32_t*)(smem + H3_BH(buf));
        const uint32_t* sBl = (const uint32_t*)(smem + H3_BL(buf));

        #pragma unroll
        for (int ks = 0; ks < 4; ks++) {
            uint4 a1[4], a2[4];
            uint2 b1[2], b2[2];
            #pragma unroll
            for (int mt = 0; mt < 4; mt++) {
                const int o = (((wr * 4 + mt) * 4 + ks) * 32 + lane) * 4;
                a1[mt] = *reinterpret_cast<const uint4*>(sAh + o);
                a2[mt] = *reinterpret_cast<const uint4*>(sAl + o);
            }
            #pragma unroll
            for (int nt = 0; nt < 2; nt++) {
                const int o = (((wc * 2 + nt) * 4 + ks) * 32 + lane) * 2;
                b1[nt] = *reinterpret_cast<const uint2*>(sBh + o);
                b2[nt] = *reinterpret_cast<const uint2*>(sBl + o);
            }
            #pragma unroll
            for (int mt = 0; mt < 4; mt++)
                #pragma unroll
                for (int nt = 0; nt < 2; nt++) {
                    mma_f16(acc[mt][nt], a1[mt].x, a1[mt].y, a1[mt].z, a1[mt].w,
                            b1[nt].x, b1[nt].y);
                    mma_f16(acc[mt][nt], a1[mt].x, a1[mt].y, a1[mt].z, a1[mt].w,
                            b2[nt].x, b2[nt].y);
                    mma_f16(acc[mt][nt], a2[mt].x, a2[mt].y, a2[mt].z, a2[mt].w,
                            b1[nt].x, b1[nt].y);
                }
        }
        __syncthreads();
    }

    // ---- tanh epilogue + z A-fragment output ----
    #pragma unroll
    for (int mt = 0; mt < 4; mt++) {
        const int mtg_glob = blockIdx.x * 8 + wr * 4 + mt;
        float v[2][4];
        #pragma unroll
        for (int nt = 0; nt < 2; nt++) {
            const int c0 = wc * 16 + nt * 8 + 2 * (lane & 3);
            const float bv0 = bias[c0], bv1 = bias[c0 + 1];
            v[nt][0] = tanhf(acc[mt][nt][0] + bv0);
            v[nt][1] = tanhf(acc[mt][nt][1] + bv1);
            v[nt][2] = tanhf(acc[mt][nt][2] + bv0);
            v[nt][3] = tanhf(acc[mt][nt][3] + bv1);
        }
        uint4 h, l;
        split2(v[0][0], v[0][1], h.x, l.x);
        split2(v[0][2], v[0][3], h.y, l.y);
        split2(v[1][0], v[1][1], h.z, l.z);
        split2(v[1][2], v[1][3], h.w, l.w);
        const size_t o = ((size_t)(mtg_glob * 4 + wc) * 32 + lane) * 4;
        *reinterpret_cast<uint4*>(dh + o) = h;
        *reinterpret_cast<uint4*>(dl + o) = l;
    }
}

// ---------------- BN finalize: parallel two-stage -----------------
__global__ void bn_stage1_kernel()
{
    const int j = threadIdx.x;
    const int b0 = blockIdx.x * 32;
    float s = 0.f, q = 0.f;
    #pragma unroll 8
    for (int r = 0; r < 32; r++) {
        s += g_ps[(size_t)(b0 + r) * HH + j];
        q += g_pq[(size_t)(b0 + r) * HH + j];
    }
    g_ps2[blockIdx.x * HH + j] = s;
    g_pq2[blockIdx.x * HH + j] = q;
}

__global__ void bn_stage2_kernel(const float* __restrict__ gamma,
                                 const float* __restrict__ beta)
{
    const int j = threadIdx.x;
    float s = 0.f, q = 0.f;
    #pragma unroll
    for (int b = 0; b < 16; b++) { s += g_ps2[b * HH + j]; q += g_pq2[b * HH + j]; }
    const float mean = s * (1.f / (float)BB);
    const float var  = q * (1.f / (float)BB) - mean * mean;
    const float inv  = rsqrtf(var + 1e-5f);
    const float sc   = gamma[j] * inv;
    g_scale[j] = sc;
    g_shift[j] = beta[j] - mean * sc;
}

// ---------------- codebook squared norms: warp per code -----------
__global__ void __launch_bounds__(256) c2_kernel(const float* __restrict__ cb)
{
    const int code = (blockIdx.x * 256 + threadIdx.x) >> 5;
    const int lane = threadIdx.x & 31;
    const float2 v = *reinterpret_cast<const float2*>(cb + (size_t)code * DE + lane * 2);
    float s = fmaf(v.x, v.x, v.y * v.y);
    #pragma unroll
    for (int off = 16; off > 0; off >>= 1)
        s += __shfl_down_sync(0xffffffff, s, off);
    if (lane == 0) g_c2[code] = s;
}

// ---------------- codebook -> fp16 hi/lo B-fragments (dist, per chunk) ---------
__global__ void cvt_cb_kernel(const float* __restrict__ cb)
{
    const int ch = blockIdx.x;
    const int tid = threadIdx.x;
    const float* src = cb + (size_t)ch * 8192;
    #pragma unroll
    for (int t = 0; t < 16; t++) {
        const int lin = t * 256 + tid;
        const int n = lin >> 5, k2 = lin & 31;
        const float2 v = *reinterpret_cast<const float2*>(src + n * 64 + 2 * k2);
        uint32_t h, l;
        split2(v.x, v.y, h, l);
        const int nt = n >> 3, nn = n & 7;
        const int ks = k2 >> 3, kk2 = k2 & 7;
        const int o = ((nt * 4 + ks) * 32 + nn * 4 + (kk2 & 3)) * 2 + (kk2 >> 2);
        g_cb1[ch * 4096 + o] = h;
        g_cb2[ch * 4096 + o] = l;
    }
}

// ================= fp16 3-term dist + argmin, column-split, 2 CTAs/SM ==========
// blockIdx.x: row tile (128 rows). blockIdx.y: code half (2048 codes, 16 chunks).
// Reduction arrays alias the B-buffer smem (dead after final chunk).
#define D_A1   0
#define D_A2   16384
#define D_B1(buf) (32768 + (buf) * 32768)
#define D_B2(buf) (D_B1(buf) + 16384)
#define D_C2   98304
#define D_REDF 32768        // aliases B1(0)
#define D_REDI 40960        // aliases B2(0)
#define D_SMEM 99328

__global__ void __launch_bounds__(256, 2) dist_argmin_mma(
    float* __restrict__ bvo, int* __restrict__ bio)
{
    extern __shared__ char smem[];
    const uint32_t sb = smem_u32(smem);
    float* c2s  = (float*)(smem + D_C2);

    const int tid  = threadIdx.x;
    const int lane = tid & 31;
    const int wid  = tid >> 5;
    const int wr   = wid >> 2;
    const int wc   = wid & 3;
    const int row0 = blockIdx.x * 128;
    const int half = blockIdx.y;
    const int ch0  = half * 16;

    // ---- async prefetch: z A-fragments + first chunk B fragments ----
    {
        const uint4* zh = (const uint4*)(g_zfh + (size_t)blockIdx.x * 4096);
        const uint4* zl = (const uint4*)(g_zfl + (size_t)blockIdx.x * 4096);
        #pragma unroll
        for (int t = 0; t < 4; t++) {
            cp16(sb + D_A1 + (t * 256 + tid) * 16, zh + t * 256 + tid);
            cp16(sb + D_A2 + (t * 256 + tid) * 16, zl + t * 256 + tid);
        }
        const uint4* g1 = (const uint4*)(g_cb1 + ch0 * 4096);
        const uint4* g2 = (const uint4*)(g_cb2 + ch0 * 4096);
        #pragma unroll
        for (int t = 0; t < 4; t++) {
            cp16(sb + D_B1(0) + (t * 256 + tid) * 16, g1 + t * 256 + tid);
            cp16(sb + D_B2(0) + (t * 256 + tid) * 16, g2 + t * 256 + tid);
        }
        if (tid < 32) cp16(sb + D_C2 + tid * 16, (const uint4*)(g_c2 + ch0 * 128) + tid);
        CP_COMMIT();
    }

    const uint32_t* sA1 = (const uint32_t*)(smem + D_A1);
    const uint32_t* sA2 = (const uint32_t*)(smem + D_A2);

    float bestv[8];
    int   besti[8];
    #pragma unroll
    for (int s = 0; s < 8; s++) { bestv[s] = 3.4e38f; besti[s] = 0; }

    for (int cc = 0; cc < 16; cc++) {
        const int ch = ch0 + cc;
        const int buf = cc & 1;
        CP_WAIT0();
        __syncthreads();

        if (cc + 1 < 16) {
            const uint4* g1 = (const uint4*)(g_cb1 + (ch + 1) * 4096);
            const uint4* g2 = (const uint4*)(g_cb2 + (ch + 1) * 4096);
            const uint32_t b1 = sb + D_B1(buf ^ 1);
            const uint32_t b2 = sb + D_B2(buf ^ 1);
            #pragma unroll
            for (int t = 0; t < 4; t++) {
                cp16(b1 + (t * 256 + tid) * 16, g1 + t * 256 + tid);
                cp16(b2 + (t * 256 + tid) * 16, g2 + t * 256 + tid);
            }
            if (tid < 32)
                cp16(sb + D_C2 + (buf ^ 1) * 512 + tid * 16,
                     (const uint4*)(g_c2 + (ch + 1) * 128) + tid);
            CP_COMMIT();
        }

        const uint32_t* sB1 = (const uint32_t*)(smem + D_B1(buf));
        const uint32_t* sB2 = (const uint32_t*)(smem + D_B2(buf));

        float acc[4][4][4];
        #pragma unroll
        for (int mt = 0; mt < 4; mt++)
            #pragma unroll
            for (int nt = 0; nt < 4; nt++)
                #pragma unroll
                for (int j = 0; j < 4; j++) acc[mt][nt][j] = 0.f;

        #pragma unroll
        for (int ks = 0; ks < 4; ks++) {
            uint4 a1[4], a2[4];
            uint2 b1[4], b2[4];
            #pragma unroll
            for (int mt = 0; mt < 4; mt++) {
                const int o = (((wr * 4 + mt) * 4 + ks) * 32 + lane) * 4;
                a1[mt] = *reinterpret_cast<const uint4*>(sA1 + o);
                a2[mt] = *reinterpret_cast<const uint4*>(sA2 + o);
            }
            #pragma unroll
            for (int nt = 0; nt < 4; nt++) {
                const int o = (((wc * 4 + nt) * 4 + ks) * 32 + lane) * 2;
                b1[nt] = *reinterpret_cast<const uint2*>(sB1 + o);
                b2[nt] = *reinterpret_cast<const uint2*>(sB2 + o);
            }
            #pragma unroll
            for (int mt = 0; mt < 4; mt++)
                #pragma unroll
                for (int nt = 0; nt < 4; nt++)
                    mma_f16(acc[mt][nt], a1[mt].x, a1[mt].y, a1[mt].z, a1[mt].w,
                            b1[nt].x, b1[nt].y);
            #pragma unroll
            for (int mt = 0; mt < 4; mt++)
                #pragma unroll
                for (int nt = 0; nt < 4; nt++)
                    mma_f16(acc[mt][nt], a1[mt].x, a1[mt].y, a1[mt].z, a1[mt].w,
                            b2[nt].x, b2[nt].y);
            #pragma unroll
            for (int mt = 0; mt < 4; mt++)
                #pragma unroll
                for (int nt = 0; nt < 4; nt++)
                    mma_f16(acc[mt][nt], a2[mt].x, a2[mt].y, a2[mt].z, a2[mt].w,
                            b1[nt].x, b1[nt].y);
        }

        const float* c2p = c2s + buf * 128;
        #pragma unroll
        for (int nt = 0; nt < 4; nt++) {
            const int ncol = wc * 32 + nt * 8 + 2 * (lane & 3);
            const float cc0 = c2p[ncol];
            const float cc1 = c2p[ncol + 1];
            const int gi = ch * 128 + ncol;
            #pragma unroll
            for (int mt = 0; mt < 4; mt++) {
                const float d0 = fmaf(-2.f, acc[mt][nt][0], cc0);
                const float d1 = fmaf(-2.f, acc[mt][nt][1], cc1);
                const float d2 = fmaf(-2.f, acc[mt][nt][2], cc0);
                const float d3 = fmaf(-2.f, acc[mt][nt][3], cc1);
                const int s0 = mt * 2, s1 = mt * 2 + 1;
                if (d0 < bestv[s0]) { bestv[s0] = d0; besti[s0] = gi; }
                if (d1 < bestv[s0]) { bestv[s0] = d1; besti[s0] = gi + 1; }
                if (d2 < bestv[s1]) { bestv[s1] = d2; besti[s1] = gi; }
                if (d3 < bestv[s1]) { bestv[s1] = d3; besti[s1] = gi + 1; }
            }
        }
        __syncthreads();
    }

    // ---- reduction (aliases dead B-buffer smem; all B reads done) ----
    float* redF = (float*)(smem + D_REDF);
    int*   redI = (int*)(smem + D_REDI);
    #pragma unroll
    for (int s = 0; s < 8; s++) {
        const int mt = s >> 1, hf = s & 1;
        const int row = wr * 64 + mt * 16 + hf * 8 + (lane >> 2);
        const int e = wc * 4 + (lane & 3);
        redF[row * 16 + e] = bestv[s];
        redI[row * 16 + e] = besti[s];
    }
    __syncthreads();
    if (tid < 128) {
        float bs = 3.4e38f;
        int   b  = 0x7fffffff;
        #pragma unroll
        for (int e = 0; e < 16; e++) {
            const float sv = redF[tid * 16 + e];
            const int   iv = redI[tid * 16 + e];
            if (sv < bs || (sv == bs && iv < b)) { bs = sv; b = iv; }
        }
        bvo[half * BB + row0 + tid] = bs;
        bio[half * BB + row0 + tid] = b;
    }
}

// ---------------- output writer (merges code halves) ----------------
__global__ void writeout_kernel(const float* __restrict__ cb,
                                const float* __restrict__ bv, const int* __restrict__ bi,
                                float* __restrict__ outf, int* __restrict__ outi,
                                int mode)
{
    const int gid = blockIdx.x * 256 + threadIdx.x;
    const int row = gid >> 6, j = gid & 63;
    const float v0 = bv[row], v1 = bv[BB + row];
    const int id = (v0 <= v1) ? bi[row] : bi[BB + row];   // tie -> half 0 (lower index)
    if (mode == 0) {
        if (j == 0) outf[row] = (float)id;
        outf[BB + gid] = cb[(size_t)id * DE + j];
    } else if (mode == 1) {
        outf[gid] = cb[(size_t)id * DE + j];
    } else {
        if (j == 0) outi[row] = id;
    }
}

// ---------------- launch -----------------------------------------------------------
extern "C" void kernel_launch(void* const* d_in, const int* in_sizes, int n_in,
                              void* d_out, int out_size)
{
    const float* x     = (const float*)d_in[0];
    const float* W1    = (const float*)d_in[1];
    const float* b1    = (const float*)d_in[2];
    const float* gamma = (const float*)d_in[3];
    const float* beta  = (const float*)d_in[4];
    const float* W2    = (const float*)d_in[5];
    const float* b2    = (const float*)d_in[6];
    const float* W3    = (const float*)d_in[7];
    const float* b3    = (const float*)d_in[8];
    const float* cb    = (const float*)d_in[9];

    float *h1p = nullptr, *psp = nullptr, *pqp = nullptr, *bvp = nullptr;
    int *bip = nullptr;
    uint32_t *a1h, *a1l, *a2h, *a2l, *a3h, *a3l, *zfh, *zfl;
    uint32_t *w1h, *w1l, *w2h, *w2l, *w3h, *w3l;
    cudaGetSymbolAddress((void**)&h1p, g_h1);
    cudaGetSymbolAddress((void**)&psp, g_ps);
    cudaGetSymbolAddress((void**)&pqp, g_pq);
    cudaGetSymbolAddress((void**)&bvp, g_bv);
    cudaGetSymbolAddress((void**)&bip, g_bi);
    cudaGetSymbolAddress((void**)&a1h, g_af1h);
    cudaGetSymbolAddress((void**)&a1l, g_af1l);
    cudaGetSymbolAddress((void**)&a2h, g_af2h);
    cudaGetSymbolAddress((void**)&a2l, g_af2l);
    cudaGetSymbolAddress((void**)&a3h, g_af3h);
    cudaGetSymbolAddress((void**)&a3l, g_af3l);
    cudaGetSymbolAddress((void**)&zfh, g_zfh);
    cudaGetSymbolAddress((void**)&zfl, g_zfl);
    cudaGetSymbolAddress((void**)&w1h, g_w1h);
    cudaGetSymbolAddress((void**)&w1l, g_w1l);
    cudaGetSymbolAddress((void**)&w2h, g_w2h);
    cudaGetSymbolAddress((void**)&w2l, g_w2l);
    cudaGetSymbolAddress((void**)&w3h, g_w3h);
    cudaGetSymbolAddress((void**)&w3l, g_w3l);

    cudaFuncSetAttribute(dist_argmin_mma, cudaFuncAttributeMaxDynamicSharedMemorySize, D_SMEM);
    cudaFuncSetAttribute(hgemm_kernel<8, 0, true, false>,
                         cudaFuncAttributeMaxDynamicSharedMemorySize, HG_SMEM(true));
    cudaFuncSetAttribute(hgemm_kernel<16, 1, false, true>,
                         cudaFuncAttributeMaxDynamicSharedMemorySize, HG_SMEM(false));
    cudaFuncSetAttribute(hgemm3_kernel, cudaFuncAttributeMaxDynamicSharedMemorySize, H3_SMEM);

    dim3 blk(256);

    // prep: operand conversions + codebook norms
    cvt_a_kernel<8, false><<<4096, blk>>>(x, a1h, a1l);
    cvt_w_kernel<<<32, blk>>>(W1, w1h, w1l, 8, 256);
    cvt_w_kernel<<<64, blk>>>(W2, w2h, w2l, 16, 256);
    cvt_w_kernel<<<16, blk>>>(W3, w3h, w3l, 16, 64);
    c2_kernel<<<512, blk>>>(cb);
    cvt_cb_kernel<<<32, blk>>>(cb);

    // h1 = x @ W1 + b1 (fp16 3-term), fp32 out + fused BN partial sums
    hgemm_kernel<8, 0, true, false><<<dim3(2, BB / 128), blk, HG_SMEM(true)>>>(
        a1h, a1l, w1h, w1l, b1, h1p, psp, pqp, nullptr, nullptr);

    // BN finalize
    bn_stage1_kernel<<<16, HH>>>();
    bn_stage2_kernel<<<1, HH>>>(gamma, beta);

    // bnrelu(h1) -> A fragments
    cvt_a_kernel<16, true><<<8192, blk>>>(h1p, a2h, a2l);

    // h2 = relu( bnrelu(h1) @ W2 + b2 ) (fp16 3-term), output AS A-fragments
    hgemm_kernel<16, 1, false, true><<<dim3(2, BB / 128), blk, HG_SMEM(false)>>>(
        a2h, a2l, w2h, w2l, b2, nullptr, nullptr, nullptr, a3h, a3l);

    // z = tanh( h2 @ W3 + b3 ) (fp16 3-term), output AS z A-fragments
    hgemm3_kernel<<<BB / 128, blk, H3_SMEM>>>(a3h, a3l, b3, zfh, zfl);

    // dist/argmin: column-split, 2 CTAs/SM
    dist_argmin_mma<<<dim3(BB / 128, 2), blk, D_SMEM>>>(bvp, bip);

    // outputs (merge halves)
    int mode;
    if      (out_size == BB * (DE + 1)) mode = 0;
    else if (out_size == BB * DE)       mode = 1;
    else                                mode = 2;
    writeout_kernel<<<(BB * DE) / 256, blk>>>(cb, bvp, bip, (float*)d_out, (int*)d_out, mode);
}